// round 11
// baseline (speedup 1.0000x reference)
#include <cuda_runtime.h>
#include <cuda_bf16.h>
#include <cstdint>
#include <math.h>

#define BB 32
#define NN 128
#define FF 10
#define DD 64
#define TK 20
#define EX 25
#define BNN 4096           // B*N
#define G2 8192            // 2*BN
#define NE (BNN*EX)        // 102400 candidate edges in layer 2
#define NSLICE 8

// ---------------- scratch (device globals: allocation-free) ----------------
__device__ float d_h[BNN*DD];
__device__ float d_si[BNN], d_sj[BNN];
__device__ float d_ei[NN], d_ej[NN], d_invn1[NN];
__device__ int   d_topi1[NN*TK];
__device__ float d_topv1[NN*TK];
__device__ float d_agg[BNN*DD];
__device__ float d_scale1[DD], d_shift1[DD];
__device__ float d_g[BNN*DD];               // gcn rows only
__device__ float d_efp[NSLICE*BNN*DD];      // ef partial sums per K-slice
__device__ float d_gn[G2*DD];               // row-normalized [gcn; ef]
__device__ float d_h2[BNN*DD];
__device__ float d_hi2[BNN], d_hj2[BNN];
__device__ float d_S[(size_t)BNN*G2];       // 128 MB cosine-score matrix
__device__ int   d_topi2[NE];
__device__ float d_topv2[NE];
__device__ int   d_cnt[BNN];
__device__ int   d_cur[BNN];
__device__ int   d_off[BNN+1];
__device__ int   d_eid[NE];
__device__ float d_sc2[NE];
__device__ float d_x3[BNN*DD];
__device__ float d_scale2[DD], d_shift2[DD];

// ---------------- helpers ----------------
__device__ __forceinline__ float lrelu(float x){ return x >= 0.f ? x : 0.2f*x; }

typedef unsigned long long ull;
__device__ __forceinline__ ull ffma2(ull a, ull b, ull c){
    ull d; asm("fma.rn.f32x2 %0, %1, %2, %3;" : "=l"(d) : "l"(a), "l"(b), "l"(c));
    return d;
}
__device__ __forceinline__ ull rep2(float x){
    ull d; asm("mov.b64 %0, {%1, %1};" : "=l"(d) : "r"(__float_as_uint(x)));
    return d;
}

// ---------------- K1: emb norms + embedding parts of attention keys ----------
__global__ void k_embprep(const float* __restrict__ emb,
                          const float* __restrict__ ai1,
                          const float* __restrict__ aj1){
    int n = blockIdx.x, t = threadIdx.x;
    float e  = emb[n*DD + t];
    float ss = e*e, vi = e*ai1[DD+t], vj = e*aj1[DD+t];
    __shared__ float sb[6];
    #pragma unroll
    for(int o=16;o>0;o>>=1){
        ss += __shfl_down_sync(0xffffffffu, ss, o);
        vi += __shfl_down_sync(0xffffffffu, vi, o);
        vj += __shfl_down_sync(0xffffffffu, vj, o);
    }
    if((t&31)==0){ int w=t>>5; sb[w]=ss; sb[2+w]=vi; sb[4+w]=vj; }
    __syncthreads();
    if(t==0){
        float nrm = sqrtf(sb[0]+sb[1]);
        d_invn1[n] = 1.f/fmaxf(nrm, 1e-12f);
        d_ei[n] = sb[2]+sb[3];
        d_ej[n] = sb[4]+sb[5];
    }
}

// ---------------- K2: cosine(emb,emb) + top-20 per node ----------------
__global__ void k_cos1(const float* __restrict__ emb){
    int i = blockIdx.x, t = threadIdx.x;            // 128 threads
    __shared__ float se[DD];
    __shared__ float sc[NN];
    __shared__ float rv[NN];
    __shared__ int   ridx[NN];
    if(t < DD) se[t] = emb[i*DD + t];
    __syncthreads();
    float dp = 0.f;
    #pragma unroll
    for(int d=0; d<DD; d++) dp += se[d]*emb[t*DD + d];
    sc[t] = dp * d_invn1[i] * d_invn1[t];
    __syncthreads();
    for(int it=0; it<TK; it++){
        rv[t] = sc[t]; ridx[t] = t;
        __syncthreads();
        for(int s=64; s>0; s>>=1){
            if(t < s){
                float v2 = rv[t+s]; int i2 = ridx[t+s];
                if(v2 > rv[t] || (v2 == rv[t] && i2 < ridx[t])){ rv[t]=v2; ridx[t]=i2; }
            }
            __syncthreads();
        }
        if(t==0){
            d_topv1[i*TK+it] = rv[0];
            d_topi1[i*TK+it] = ridx[0];
            sc[ridx[0]] = -INFINITY;
        }
        __syncthreads();
    }
}

// ---------------- K3: h = x@W1, si/sj scalars (4 rows/block) ----------------
__global__ void k_h(const float* __restrict__ data, const float* __restrict__ W1,
                    const float* __restrict__ ai1, const float* __restrict__ aj1){
    int t = threadIdx.x;
    int g = t>>6, d = t&63;
    int r = blockIdx.x*4 + g;
    __shared__ float sx[4][FF];
    __shared__ float svi[8], svj[8];
    if(d < FF) sx[g][d] = data[r*FF + d];
    __syncthreads();
    float h = 0.f;
    #pragma unroll
    for(int f=0; f<FF; f++) h += sx[g][f]*W1[f*DD + d];
    d_h[r*DD + d] = h;
    float vi = h*ai1[d], vj = h*aj1[d];
    #pragma unroll
    for(int o=16;o>0;o>>=1){
        vi += __shfl_down_sync(0xffffffffu, vi, o);
        vj += __shfl_down_sync(0xffffffffu, vj, o);
    }
    if((t&31)==0){ svi[t>>5]=vi; svj[t>>5]=vj; }
    __syncthreads();
    if(d==0){
        d_si[r] = svi[2*g]+svi[2*g+1] + d_ei[r & (NN-1)];
        d_sj[r] = svj[2*g]+svj[2*g+1] + d_ej[r & (NN-1)];
    }
}

// ---------------- K4: layer-1 edge softmax + aggregation (4 rows/block) -----
__global__ void k_attn1(const float* __restrict__ bias1){
    int t = threadIdx.x;
    int g = t>>6, d = t&63;
    int r = blockIdx.x*4 + g;
    int b = r >> 7, i = r & (NN-1);
    __shared__ int   ssrc[4][TK];
    __shared__ float sal[4][TK];
    if(d < TK){
        int sn = d_topi1[i*TK + d];
        int s  = (b<<7) + sn;
        ssrc[g][d] = s;
        sal[g][d]  = lrelu(d_si[r] + d_sj[s]) * d_topv1[i*TK + d];
    }
    __syncthreads();
    if(d == 0){
        float m = -INFINITY;
        for(int k=0;k<TK;k++) m = fmaxf(m, sal[g][k]);
        float e[TK], sum = 0.f;
        for(int k=0;k<TK;k++){ e[k] = expf(sal[g][k]-m); sum += e[k]; }
        float inv = 1.f/fmaxf(sum, 1e-12f);
        for(int k=0;k<TK;k++) sal[g][k] = e[k]*inv;
    }
    __syncthreads();
    float a = 0.f;
    #pragma unroll
    for(int k=0;k<TK;k++) a += sal[g][k]*d_h[ssrc[g][k]*DD + d];
    d_agg[r*DD + d] = a + bias1[d];
}

// ---------------- batchnorm stats (two-pass, per channel) ----------------
__global__ void k_stats1(const float* __restrict__ gamma, const float* __restrict__ beta){
    int d = blockIdx.x, t = threadIdx.x;            // 256 threads
    __shared__ float sb[8];
    __shared__ float smu;
    float s = 0.f;
    for(int r=t; r<BNN; r+=256) s += d_agg[r*DD + d];
    #pragma unroll
    for(int o=16;o>0;o>>=1) s += __shfl_down_sync(0xffffffffu, s, o);
    if((t&31)==0) sb[t>>5] = s;
    __syncthreads();
    if(t==0){ float tot=0; for(int w=0;w<8;w++) tot+=sb[w]; smu = tot*(1.f/BNN); }
    __syncthreads();
    float mu = smu;
    float q = 0.f;
    for(int r=t; r<BNN; r+=256){ float x = d_agg[r*DD + d] - mu; q += x*x; }
    #pragma unroll
    for(int o=16;o>0;o>>=1) q += __shfl_down_sync(0xffffffffu, q, o);
    if((t&31)==0) sb[t>>5] = q;
    __syncthreads();
    if(t==0){
        float tot=0; for(int w=0;w<8;w++) tot+=sb[w];
        float var = tot*(1.f/BNN);
        float sc  = gamma[d]/sqrtf(var + 1e-5f);
        d_scale1[d] = sc; d_shift1[d] = beta[d] - mu*sc;
    }
}

__global__ void k_bnrelu(){
    int idx = blockIdx.x*256 + threadIdx.x;
    int d = idx & 63;
    d_g[idx] = fmaxf(d_scale1[d]*d_agg[idx] + d_shift1[d], 0.f);
}

// ---------------- K8: ef = P^T @ gcn (64-j tiles, 8 K-slices, prefetch) -----
__global__ void __launch_bounds__(128) k_ef(const float* __restrict__ P){
    __shared__ float As[64][68];   // [k_local][j_local] = P[k][j0+j]
    __shared__ float Bs[64][68];   // [k_local][d]       = gcn[k][d]
    int t = threadIdx.x;
    int j0 = blockIdx.x*64;
    int slice = blockIdx.y;
    int tx = t & 7, ty = t >> 3;   // tx: d octet, ty: j quad
    float4 pa[8], pb[8];
    int ib = slice*512;
    #pragma unroll
    for(int u=0; u<8; u++){
        int f = t*8+u; int k = f>>4; int cq = f&15;
        pa[u] = *(const float4*)&P[(size_t)(ib+k)*BNN + j0 + cq*4];
        pb[u] = *(const float4*)&d_g[(ib+k)*DD + cq*4];
    }
    ull cp[4][4] = {};
    for(int cc=0; cc<8; cc++){
        #pragma unroll
        for(int u=0; u<8; u++){
            int f = t*8+u; int k = f>>4; int cq = f&15;
            *(float4*)&As[k][cq*4] = pa[u];
            *(float4*)&Bs[k][cq*4] = pb[u];
        }
        __syncthreads();
        if(cc < 7){
            int ib2 = slice*512 + (cc+1)*64;
            #pragma unroll
            for(int u=0; u<8; u++){
                int f = t*8+u; int k = f>>4; int cq = f&15;
                pa[u] = *(const float4*)&P[(size_t)(ib2+k)*BNN + j0 + cq*4];
                pb[u] = *(const float4*)&d_g[(ib2+k)*DD + cq*4];
            }
        }
        #pragma unroll
        for(int k=0; k<64; k++){
            float4 a = *(float4*)&As[k][ty*4];
            ulonglong2 b01 = *(ulonglong2*)&Bs[k][tx*8];
            ulonglong2 b23 = *(ulonglong2*)&Bs[k][tx*8+4];
            ull ra;
            ra = rep2(a.x);
            cp[0][0]=ffma2(ra,b01.x,cp[0][0]); cp[0][1]=ffma2(ra,b01.y,cp[0][1]);
            cp[0][2]=ffma2(ra,b23.x,cp[0][2]); cp[0][3]=ffma2(ra,b23.y,cp[0][3]);
            ra = rep2(a.y);
            cp[1][0]=ffma2(ra,b01.x,cp[1][0]); cp[1][1]=ffma2(ra,b01.y,cp[1][1]);
            cp[1][2]=ffma2(ra,b23.x,cp[1][2]); cp[1][3]=ffma2(ra,b23.y,cp[1][3]);
            ra = rep2(a.z);
            cp[2][0]=ffma2(ra,b01.x,cp[2][0]); cp[2][1]=ffma2(ra,b01.y,cp[2][1]);
            cp[2][2]=ffma2(ra,b23.x,cp[2][2]); cp[2][3]=ffma2(ra,b23.y,cp[2][3]);
            ra = rep2(a.w);
            cp[3][0]=ffma2(ra,b01.x,cp[3][0]); cp[3][1]=ffma2(ra,b01.y,cp[3][1]);
            cp[3][2]=ffma2(ra,b23.x,cp[3][2]); cp[3][3]=ffma2(ra,b23.y,cp[3][3]);
        }
        __syncthreads();
    }
    float* outp = &d_efp[(size_t)slice*BNN*DD];
    #pragma unroll
    for(int m=0;m<4;m++){
        int row = j0 + ty*4 + m;
        ulonglong2 o1; o1.x = cp[m][0]; o1.y = cp[m][1];
        ulonglong2 o2; o2.x = cp[m][2]; o2.y = cp[m][3];
        *(ulonglong2*)&outp[row*DD + tx*8]     = o1;
        *(ulonglong2*)&outp[row*DD + tx*8 + 4] = o2;
    }
}

// ---------------- K9: row-normalize [gcn; ef] + zero CSR counters -----------
__global__ void k_gnorm(){
    int t = threadIdx.x;
    // fused: zero CSR counters (first 16 blocks)
    int gid = blockIdx.x*256 + t;
    if(gid < BNN){ d_cnt[gid] = 0; d_cur[gid] = 0; }
    int g = t>>6, d = t&63;
    int r = blockIdx.x*4 + g;
    __shared__ float sb[8];
    float v;
    if(r < BNN) v = d_g[r*DD + d];
    else {
        int rr = r - BNN;
        v = 0.f;
        #pragma unroll
        for(int s=0; s<NSLICE; s++) v += d_efp[(size_t)s*BNN*DD + rr*DD + d];
    }
    float ss = v*v;
    #pragma unroll
    for(int o=16;o>0;o>>=1) ss += __shfl_down_sync(0xffffffffu, ss, o);
    if((t&31)==0) sb[t>>5] = ss;
    __syncthreads();
    float inv = 1.f/fmaxf(sqrtf(sb[2*g]+sb[2*g+1]), 1e-12f);
    d_gn[r*DD + d] = v*inv;
}

// ---------------- K10a: right half S[:, 4096:8192] (128x64 tiles) -----------
__global__ void __launch_bounds__(128) k_sgemm(int joff){
    __shared__ float As[64][132];  // [d][m] m=128, transposed on load
    __shared__ float Bs[64][68];   // [d][n] n=64,  transposed on load
    int t = threadIdx.x;
    int j0 = joff + blockIdx.x*64, i0 = blockIdx.y*128;
    #pragma unroll
    for(int u=0; u<16; u++){
        float4 va = *(const float4*)&d_gn[(i0+t)*DD + u*4];
        As[u*4+0][t]=va.x; As[u*4+1][t]=va.y; As[u*4+2][t]=va.z; As[u*4+3][t]=va.w;
    }
    #pragma unroll
    for(int u=0; u<8; u++){
        int f = t*8+u; int rr = f>>4; int cq = f&15;
        float4 vb = *(const float4*)&d_gn[(j0+rr)*DD + cq*4];
        Bs[cq*4+0][rr]=vb.x; Bs[cq*4+1][rr]=vb.y; Bs[cq*4+2][rr]=vb.z; Bs[cq*4+3][rr]=vb.w;
    }
    __syncthreads();
    int tx = t & 7, ty = t >> 3;   // tx: n octet, ty: m octet (16)
    ull cp[8][4] = {};
    #pragma unroll
    for(int k=0; k<64; k++){
        float4 a0 = *(float4*)&As[k][ty*8];
        float4 a1 = *(float4*)&As[k][ty*8+4];
        ulonglong2 b01 = *(ulonglong2*)&Bs[k][tx*8];
        ulonglong2 b23 = *(ulonglong2*)&Bs[k][tx*8+4];
        ull ra;
        ra=rep2(a0.x);
        cp[0][0]=ffma2(ra,b01.x,cp[0][0]); cp[0][1]=ffma2(ra,b01.y,cp[0][1]);
        cp[0][2]=ffma2(ra,b23.x,cp[0][2]); cp[0][3]=ffma2(ra,b23.y,cp[0][3]);
        ra=rep2(a0.y);
        cp[1][0]=ffma2(ra,b01.x,cp[1][0]); cp[1][1]=ffma2(ra,b01.y,cp[1][1]);
        cp[1][2]=ffma2(ra,b23.x,cp[1][2]); cp[1][3]=ffma2(ra,b23.y,cp[1][3]);
        ra=rep2(a0.z);
        cp[2][0]=ffma2(ra,b01.x,cp[2][0]); cp[2][1]=ffma2(ra,b01.y,cp[2][1]);
        cp[2][2]=ffma2(ra,b23.x,cp[2][2]); cp[2][3]=ffma2(ra,b23.y,cp[2][3]);
        ra=rep2(a0.w);
        cp[3][0]=ffma2(ra,b01.x,cp[3][0]); cp[3][1]=ffma2(ra,b01.y,cp[3][1]);
        cp[3][2]=ffma2(ra,b23.x,cp[3][2]); cp[3][3]=ffma2(ra,b23.y,cp[3][3]);
        ra=rep2(a1.x);
        cp[4][0]=ffma2(ra,b01.x,cp[4][0]); cp[4][1]=ffma2(ra,b01.y,cp[4][1]);
        cp[4][2]=ffma2(ra,b23.x,cp[4][2]); cp[4][3]=ffma2(ra,b23.y,cp[4][3]);
        ra=rep2(a1.y);
        cp[5][0]=ffma2(ra,b01.x,cp[5][0]); cp[5][1]=ffma2(ra,b01.y,cp[5][1]);
        cp[5][2]=ffma2(ra,b23.x,cp[5][2]); cp[5][3]=ffma2(ra,b23.y,cp[5][3]);
        ra=rep2(a1.z);
        cp[6][0]=ffma2(ra,b01.x,cp[6][0]); cp[6][1]=ffma2(ra,b01.y,cp[6][1]);
        cp[6][2]=ffma2(ra,b23.x,cp[6][2]); cp[6][3]=ffma2(ra,b23.y,cp[6][3]);
        ra=rep2(a1.w);
        cp[7][0]=ffma2(ra,b01.x,cp[7][0]); cp[7][1]=ffma2(ra,b01.y,cp[7][1]);
        cp[7][2]=ffma2(ra,b23.x,cp[7][2]); cp[7][3]=ffma2(ra,b23.y,cp[7][3]);
    }
    #pragma unroll
    for(int m=0;m<8;m++){
        int row = i0 + ty*8 + m;
        ulonglong2 o1; o1.x = cp[m][0]; o1.y = cp[m][1];
        ulonglong2 o2; o2.x = cp[m][2]; o2.y = cp[m][3];
        *(ulonglong2*)&d_S[(size_t)row*G2 + j0 + tx*8]     = o1;
        *(ulonglong2*)&d_S[(size_t)row*G2 + j0 + tx*8 + 4] = o2;
    }
}

// ---------------- K10b: symmetric left half S[:, 0:4096] (128x128 tiles) ----
// Computes only lower-triangular tile pairs (jb <= ib); mirrors off-diagonal.
#define SGS_SMEM (2*64*132*4)
__global__ void __launch_bounds__(256) k_sgemm_sym(){
    extern __shared__ float smp[];
    float* As = smp;             // [64][132]
    float* Bs = smp + 64*132;    // [64][132]
    int t = threadIdx.x;
    // triangular decode: idx -> (ib, jb), jb <= ib, ib in 0..31
    int idx = blockIdx.x;
    int ib = (int)((sqrtf(8.f*idx + 1.f) - 1.f)*0.5f);
    while((ib+1)*(ib+2)/2 <= idx) ib++;
    while(ib*(ib+1)/2 > idx) ib--;
    int jb = idx - ib*(ib+1)/2;
    int i0 = ib*128, j0 = jb*128;

    // load: threads 0-127 stage A rows, 128-255 stage B rows (transposed)
    {
        int lr = t & 127;
        const float* src = (t < 128) ? &d_gn[(i0+lr)*DD] : &d_gn[(j0+lr)*DD];
        float* dst = (t < 128) ? As : Bs;
        #pragma unroll
        for(int u=0; u<16; u++){
            float4 va = *(const float4*)&src[u*4];
            dst[(u*4+0)*132+lr]=va.x; dst[(u*4+1)*132+lr]=va.y;
            dst[(u*4+2)*132+lr]=va.z; dst[(u*4+3)*132+lr]=va.w;
        }
    }
    __syncthreads();
    int tx = t & 15, ty = t >> 4;   // tx: n octet (16), ty: m octet (16)
    ull cp[8][4] = {};
    #pragma unroll
    for(int k=0; k<64; k++){
        float4 a0 = *(float4*)&As[k*132 + ty*8];
        float4 a1 = *(float4*)&As[k*132 + ty*8 + 4];
        ulonglong2 b01 = *(ulonglong2*)&Bs[k*132 + tx*8];
        ulonglong2 b23 = *(ulonglong2*)&Bs[k*132 + tx*8 + 4];
        ull ra;
        ra=rep2(a0.x);
        cp[0][0]=ffma2(ra,b01.x,cp[0][0]); cp[0][1]=ffma2(ra,b01.y,cp[0][1]);
        cp[0][2]=ffma2(ra,b23.x,cp[0][2]); cp[0][3]=ffma2(ra,b23.y,cp[0][3]);
        ra=rep2(a0.y);
        cp[1][0]=ffma2(ra,b01.x,cp[1][0]); cp[1][1]=ffma2(ra,b01.y,cp[1][1]);
        cp[1][2]=ffma2(ra,b23.x,cp[1][2]); cp[1][3]=ffma2(ra,b23.y,cp[1][3]);
        ra=rep2(a0.z);
        cp[2][0]=ffma2(ra,b01.x,cp[2][0]); cp[2][1]=ffma2(ra,b01.y,cp[2][1]);
        cp[2][2]=ffma2(ra,b23.x,cp[2][2]); cp[2][3]=ffma2(ra,b23.y,cp[2][3]);
        ra=rep2(a0.w);
        cp[3][0]=ffma2(ra,b01.x,cp[3][0]); cp[3][1]=ffma2(ra,b01.y,cp[3][1]);
        cp[3][2]=ffma2(ra,b23.x,cp[3][2]); cp[3][3]=ffma2(ra,b23.y,cp[3][3]);
        ra=rep2(a1.x);
        cp[4][0]=ffma2(ra,b01.x,cp[4][0]); cp[4][1]=ffma2(ra,b01.y,cp[4][1]);
        cp[4][2]=ffma2(ra,b23.x,cp[4][2]); cp[4][3]=ffma2(ra,b23.y,cp[4][3]);
        ra=rep2(a1.y);
        cp[5][0]=ffma2(ra,b01.x,cp[5][0]); cp[5][1]=ffma2(ra,b01.y,cp[5][1]);
        cp[5][2]=ffma2(ra,b23.x,cp[5][2]); cp[5][3]=ffma2(ra,b23.y,cp[5][3]);
        ra=rep2(a1.z);
        cp[6][0]=ffma2(ra,b01.x,cp[6][0]); cp[6][1]=ffma2(ra,b01.y,cp[6][1]);
        cp[6][2]=ffma2(ra,b23.x,cp[6][2]); cp[6][3]=ffma2(ra,b23.y,cp[6][3]);
        ra=rep2(a1.w);
        cp[7][0]=ffma2(ra,b01.x,cp[7][0]); cp[7][1]=ffma2(ra,b01.y,cp[7][1]);
        cp[7][2]=ffma2(ra,b23.x,cp[7][2]); cp[7][3]=ffma2(ra,b23.y,cp[7][3]);
    }
    // direct write: rows i0.., cols j0..
    #pragma unroll
    for(int m=0;m<8;m++){
        int row = i0 + ty*8 + m;
        ulonglong2 o1; o1.x = cp[m][0]; o1.y = cp[m][1];
        ulonglong2 o2; o2.x = cp[m][2]; o2.y = cp[m][3];
        *(ulonglong2*)&d_S[(size_t)row*G2 + j0 + tx*8]     = o1;
        *(ulonglong2*)&d_S[(size_t)row*G2 + j0 + tx*8 + 4] = o2;
    }
    // mirror write (off-diagonal only): S[j][i] = S[i][j]
    if(ib != jb){
        #pragma unroll
        for(int m=0;m<8;m++){
            int col = i0 + ty*8 + m;
            #pragma unroll
            for(int q=0;q<4;q++){
                float2 f = *(float2*)&cp[m][q];
                int r0 = j0 + tx*8 + 2*q;
                d_S[(size_t)r0*G2 + col]     = f.x;
                d_S[(size_t)(r0+1)*G2 + col] = f.y;
            }
        }
    }
}

// ---------------- K11: top-25 per row (register-resident, 1 bar/pick) -------
__global__ void k_top25(){
    int r = blockIdx.x, t = threadIdx.x;     // 256 threads
    float4 v[8];
    #pragma unroll
    for(int u=0; u<8; u++)
        v[u] = *(const float4*)&d_S[(size_t)r*G2 + (t + u*256)*4];
    unsigned rem = 0;
    float bv; int bi;
    #define RESCAN() do{ \
        bv = -INFINITY; bi = 0x7fffffff; \
        _Pragma("unroll") \
        for(int u=0;u<8;u++){ \
            int base = 4*(t + u*256); \
            float x0 = (rem&(1u<<(u*4+0))) ? -INFINITY : v[u].x; if(x0>bv){bv=x0;bi=base;} \
            float x1 = (rem&(1u<<(u*4+1))) ? -INFINITY : v[u].y; if(x1>bv){bv=x1;bi=base+1;} \
            float x2 = (rem&(1u<<(u*4+2))) ? -INFINITY : v[u].z; if(x2>bv){bv=x2;bi=base+2;} \
            float x3 = (rem&(1u<<(u*4+3))) ? -INFINITY : v[u].w; if(x3>bv){bv=x3;bi=base+3;} \
        } }while(0)
    RESCAN();
    __shared__ float swv[2][8];
    __shared__ int   swi[2][8];
    for(int it=0; it<EX; it++){
        float wv = bv; int wi = bi;
        #pragma unroll
        for(int o=16;o>0;o>>=1){
            float ov = __shfl_xor_sync(0xffffffffu, wv, o);
            int   oi = __shfl_xor_sync(0xffffffffu, wi, o);
            if(ov > wv || (ov == wv && oi < wi)){ wv = ov; wi = oi; }
        }
        int p = it & 1;
        if((t&31)==0){ swv[p][t>>5] = wv; swi[p][t>>5] = wi; }
        __syncthreads();
        float gm = swv[p][0]; int gi = swi[p][0];
        #pragma unroll
        for(int w=1;w<8;w++){
            if(swv[p][w] > gm || (swv[p][w] == gm && swi[p][w] < gi)){ gm = swv[p][w]; gi = swi[p][w]; }
        }
        if(t==0){
            d_topv2[r*EX+it] = gm;
            d_topi2[r*EX+it] = gi;
            if(gi < BNN) atomicAdd(&d_cnt[gi], 1);   // fused histogram
        }
        if(bi == gi){
            int q = gi >> 2;
            rem |= 1u << (((q >> 8) << 2) | (gi & 3));
            RESCAN();
        }
    }
    #undef RESCAN
}

// ---------------- K12: h2 = g[:BN] @ W2 + attention scalars (4 rows/blk) ----
__global__ void k_h2(const float* __restrict__ W2,
                     const float* __restrict__ ai2, const float* __restrict__ aj2){
    int t = threadIdx.x;
    int g = t>>6, d = t&63;
    int r = blockIdx.x*4 + g;
    __shared__ float sg[4][DD];
    __shared__ float svi[8], svj[8];
    sg[g][d] = d_g[r*DD + d];
    __syncthreads();
    float h = 0.f;
    #pragma unroll
    for(int k=0;k<DD;k++) h += sg[g][k]*W2[k*DD + d];
    d_h2[r*DD + d] = h;
    float vi = h*ai2[d], vj = h*aj2[d];
    #pragma unroll
    for(int o=16;o>0;o>>=1){
        vi += __shfl_down_sync(0xffffffffu, vi, o);
        vj += __shfl_down_sync(0xffffffffu, vj, o);
    }
    if((t&31)==0){ svi[t>>5]=vi; svj[t>>5]=vj; }
    __syncthreads();
    if(d==0){ d_hi2[r] = svi[2*g]+svi[2*g+1]; d_hj2[r] = svj[2*g]+svj[2*g+1]; }
}

// ---------------- K13/K14: CSR build (scan + scatter) -----------------------
__global__ void k_scan(){       // single block, 256 threads
    __shared__ int ss[256];
    int t = threadIdx.x;
    int c[16]; int s = 0;
    #pragma unroll
    for(int i=0;i<16;i++){ int x = d_cnt[t*16+i]; c[i] = s; s += x; }
    ss[t] = s;
    __syncthreads();
    for(int off=1; off<256; off<<=1){
        int v = (t>=off) ? ss[t-off] : 0;
        __syncthreads();
        ss[t] += v;
        __syncthreads();
    }
    int base = (t==0) ? 0 : ss[t-1];
    #pragma unroll
    for(int i=0;i<16;i++) d_off[t*16+i] = base + c[i];
    if(t==255) d_off[BNN] = ss[255];
}
__global__ void k_scatter(){
    int e = blockIdx.x*256 + threadIdx.x;
    int dst = d_topi2[e];
    if(dst < BNN){
        int p = atomicAdd(&d_cur[dst], 1);
        d_eid[d_off[dst] + p] = e;
    }
}

// ---------------- K15: fused segment softmax + gather + x3 ------------------
__global__ void k_seg(const float* __restrict__ bias2, const float* __restrict__ emb){
    int r = blockIdx.x, t = threadIdx.x;    // 64 threads
    int start = d_off[r], end = d_off[r+1];
    __shared__ float sred[2];
    __shared__ float sal[64];
    __shared__ int   ssrc[64];
    float hi = d_hi2[r];
    float m = -INFINITY;
    for(int e=start+t; e<end; e+=64){
        int eid = d_eid[e]; int src = eid/EX;
        float sc = lrelu(hi + d_hj2[src]) * d_topv2[eid];
        d_sc2[e] = sc;
        m = fmaxf(m, sc);
    }
    #pragma unroll
    for(int o=16;o>0;o>>=1) m = fmaxf(m, __shfl_down_sync(0xffffffffu, m, o));
    if((t&31)==0) sred[t>>5] = m;
    __syncthreads();
    m = fmaxf(sred[0], sred[1]);
    __syncthreads();
    float s = 0.f;
    for(int e=start+t; e<end; e+=64) s += expf(d_sc2[e]-m);
    #pragma unroll
    for(int o=16;o>0;o>>=1) s += __shfl_down_sync(0xffffffffu, s, o);
    if((t&31)==0) sred[t>>5] = s;
    __syncthreads();
    float inv = 1.f/fmaxf(sred[0]+sred[1], 1e-12f);
    float acc = 0.f;
    for(int c0=start; c0<end; c0+=64){
        __syncthreads();
        int e = c0 + t;
        if(e < end){
            int eid = d_eid[e];
            ssrc[t] = eid/EX;
            sal[t]  = expf(d_sc2[e]-m)*inv;
        }
        __syncthreads();
        int cnt = min(64, end - c0);
        for(int k=0;k<cnt;k++) acc += sal[k]*d_h2[ssrc[k]*DD + t];
    }
    // fused: x3 = relu(acc + bias2) * emb
    float x = fmaxf(acc + bias2[t], 0.f);
    d_x3[r*DD + t] = x * emb[(r & (NN-1))*DD + t];
}

__global__ void k_stats2(const float* __restrict__ gamma, const float* __restrict__ beta){
    int d = blockIdx.x, t = threadIdx.x;
    __shared__ float sb[8];
    __shared__ float smu;
    float s = 0.f;
    for(int r=t; r<BNN; r+=256) s += d_x3[r*DD + d];
    #pragma unroll
    for(int o=16;o>0;o>>=1) s += __shfl_down_sync(0xffffffffu, s, o);
    if((t&31)==0) sb[t>>5] = s;
    __syncthreads();
    if(t==0){ float tot=0; for(int w=0;w<8;w++) tot+=sb[w]; smu = tot*(1.f/BNN); }
    __syncthreads();
    float mu = smu;
    float q = 0.f;
    for(int r=t; r<BNN; r+=256){ float x = d_x3[r*DD + d] - mu; q += x*x; }
    #pragma unroll
    for(int o=16;o>0;o>>=1) q += __shfl_down_sync(0xffffffffu, q, o);
    if((t&31)==0) sb[t>>5] = q;
    __syncthreads();
    if(t==0){
        float tot=0; for(int w=0;w<8;w++) tot+=sb[w];
        float var = tot*(1.f/BNN);
        float sc  = gamma[d]/sqrtf(var + 1e-5f);
        d_scale2[d] = sc; d_shift2[d] = beta[d] - mu*sc;
    }
}

// ---------------- K17: output head (4 rows/block) ----------------
__global__ void k_out(const float* __restrict__ Wout, const float* __restrict__ bout,
                      float* __restrict__ out){
    int t = threadIdx.x;
    int g = t>>6, d = t&63;
    int r = blockIdx.x*4 + g;
    __shared__ float sb[8];
    float x = fmaxf(d_scale2[d]*d_x3[r*DD + d] + d_shift2[d], 0.f);
    float v = x * Wout[d];
    #pragma unroll
    for(int o=16;o>0;o>>=1) v += __shfl_down_sync(0xffffffffu, v, o);
    if((t&31)==0) sb[t>>5] = v;
    __syncthreads();
    if(d==0) out[r] = sb[2*g]+sb[2*g+1] + bout[0];
}

// ---------------- launch ----------------
extern "C" void kernel_launch(void* const* d_in, const int* in_sizes, int n_in,
                              void* d_out, int out_size){
    (void)in_sizes; (void)n_in; (void)out_size;
    const float* data  = (const float*)d_in[0];
    const float* emb   = (const float*)d_in[1];
    const float* W1    = (const float*)d_in[2];
    const float* ai1   = (const float*)d_in[3];
    const float* aj1   = (const float*)d_in[4];
    const float* bias1 = (const float*)d_in[5];
    const float* bn1g  = (const float*)d_in[6];
    const float* bn1b  = (const float*)d_in[7];
    const float* P     = (const float*)d_in[8];
    const float* W2    = (const float*)d_in[9];
    const float* ai2   = (const float*)d_in[10];
    const float* aj2   = (const float*)d_in[11];
    const float* bias2 = (const float*)d_in[12];
    const float* bnOg  = (const float*)d_in[13];
    const float* bnOb  = (const float*)d_in[14];
    const float* Wout  = (const float*)d_in[15];
    const float* bout  = (const float*)d_in[16];
    float* out = (float*)d_out;

    static int smem_set = 0;
    if(!smem_set){
        cudaFuncSetAttribute(k_sgemm_sym, cudaFuncAttributeMaxDynamicSharedMemorySize, SGS_SMEM);
        smem_set = 1;
    }

    k_embprep  <<<NN, DD>>>(emb, ai1, aj1);
    k_cos1     <<<NN, NN>>>(emb);
    k_h        <<<BNN/4, 256>>>(data, W1, ai1, aj1);
    k_attn1    <<<BNN/4, 256>>>(bias1);
    k_stats1   <<<DD, 256>>>(bn1g, bn1b);
    k_bnrelu   <<<BNN*DD/256, 256>>>();
    k_ef       <<<dim3(64, NSLICE), 128>>>(P);
    k_gnorm    <<<G2/4, 256>>>();
    k_sgemm_sym<<<528, 256, SGS_SMEM>>>();
    k_sgemm    <<<dim3(64, 32), 128>>>(BNN);
    k_top25    <<<BNN, 256>>>();
    k_h2       <<<BNN/4, 256>>>(W2, ai2, aj2);
    k_scan     <<<1, 256>>>();
    k_scatter  <<<NE/256, 256>>>();
    k_seg      <<<BNN, 64>>>(bias2, emb);
    k_stats2   <<<DD, 256>>>(bnOg, bnOb);
    k_out      <<<BNN/4, 256>>>(Wout, bout, out);
}

// round 12
// speedup vs baseline: 1.2295x; 1.2295x over previous
#include <cuda_runtime.h>
#include <cuda_bf16.h>
#include <cstdint>
#include <math.h>

#define BB 32
#define NN 128
#define FF 10
#define DD 64
#define TK 20
#define EX 25
#define BNN 4096           // B*N
#define G2 8192            // 2*BN
#define NE (BNN*EX)        // 102400 candidate edges in layer 2
#define NSLICE 8

// ---------------- scratch (device globals: allocation-free) ----------------
__device__ float d_h[BNN*DD];
__device__ float d_si[BNN], d_sj[BNN];
__device__ float d_ei[NN], d_ej[NN], d_invn1[NN];
__device__ int   d_topi1[NN*TK];
__device__ float d_topv1[NN*TK];
__device__ float d_agg[BNN*DD];
__device__ float d_scale1[DD], d_shift1[DD];
__device__ float d_g[BNN*DD];               // gcn rows only
__device__ float d_efp[NSLICE*BNN*DD];      // ef partial sums per K-slice
__device__ float d_gn[G2*DD];               // row-normalized [gcn; ef]
__device__ float d_h2[BNN*DD];
__device__ float d_hi2[BNN], d_hj2[BNN];
__device__ float d_S[(size_t)BNN*G2];       // 128 MB cosine-score matrix
__device__ int   d_topi2[NE];
__device__ float d_topv2[NE];
__device__ int   d_cnt[BNN];
__device__ int   d_cur[BNN];
__device__ int   d_off[BNN+1];
__device__ int   d_eid[NE];
__device__ float d_sc2[NE];
__device__ float d_x3[BNN*DD];
__device__ float d_scale2[DD], d_shift2[DD];

// ---------------- helpers ----------------
__device__ __forceinline__ float lrelu(float x){ return x >= 0.f ? x : 0.2f*x; }

typedef unsigned long long ull;
__device__ __forceinline__ ull ffma2(ull a, ull b, ull c){
    ull d; asm("fma.rn.f32x2 %0, %1, %2, %3;" : "=l"(d) : "l"(a), "l"(b), "l"(c));
    return d;
}
__device__ __forceinline__ ull rep2(float x){
    ull d; asm("mov.b64 %0, {%1, %1};" : "=l"(d) : "r"(__float_as_uint(x)));
    return d;
}

// ---------------- K1: emb norms + embedding parts of attention keys ----------
__global__ void k_embprep(const float* __restrict__ emb,
                          const float* __restrict__ ai1,
                          const float* __restrict__ aj1){
    int n = blockIdx.x, t = threadIdx.x;
    float e  = emb[n*DD + t];
    float ss = e*e, vi = e*ai1[DD+t], vj = e*aj1[DD+t];
    __shared__ float sb[6];
    #pragma unroll
    for(int o=16;o>0;o>>=1){
        ss += __shfl_down_sync(0xffffffffu, ss, o);
        vi += __shfl_down_sync(0xffffffffu, vi, o);
        vj += __shfl_down_sync(0xffffffffu, vj, o);
    }
    if((t&31)==0){ int w=t>>5; sb[w]=ss; sb[2+w]=vi; sb[4+w]=vj; }
    __syncthreads();
    if(t==0){
        float nrm = sqrtf(sb[0]+sb[1]);
        d_invn1[n] = 1.f/fmaxf(nrm, 1e-12f);
        d_ei[n] = sb[2]+sb[3];
        d_ej[n] = sb[4]+sb[5];
    }
}

// ---------------- K2: cosine(emb,emb) + top-20 per node ----------------
__global__ void k_cos1(const float* __restrict__ emb){
    int i = blockIdx.x, t = threadIdx.x;            // 128 threads
    __shared__ float se[DD];
    __shared__ float sc[NN];
    __shared__ float rv[NN];
    __shared__ int   ridx[NN];
    if(t < DD) se[t] = emb[i*DD + t];
    __syncthreads();
    float dp = 0.f;
    #pragma unroll
    for(int d=0; d<DD; d++) dp += se[d]*emb[t*DD + d];
    sc[t] = dp * d_invn1[i] * d_invn1[t];
    __syncthreads();
    for(int it=0; it<TK; it++){
        rv[t] = sc[t]; ridx[t] = t;
        __syncthreads();
        for(int s=64; s>0; s>>=1){
            if(t < s){
                float v2 = rv[t+s]; int i2 = ridx[t+s];
                if(v2 > rv[t] || (v2 == rv[t] && i2 < ridx[t])){ rv[t]=v2; ridx[t]=i2; }
            }
            __syncthreads();
        }
        if(t==0){
            d_topv1[i*TK+it] = rv[0];
            d_topi1[i*TK+it] = ridx[0];
            sc[ridx[0]] = -INFINITY;
        }
        __syncthreads();
    }
}

// ---------------- K3: h = x@W1, si/sj scalars (4 rows/block) ----------------
__global__ void k_h(const float* __restrict__ data, const float* __restrict__ W1,
                    const float* __restrict__ ai1, const float* __restrict__ aj1){
    int t = threadIdx.x;
    int g = t>>6, d = t&63;
    int r = blockIdx.x*4 + g;
    __shared__ float sx[4][FF];
    __shared__ float svi[8], svj[8];
    if(d < FF) sx[g][d] = data[r*FF + d];
    __syncthreads();
    float h = 0.f;
    #pragma unroll
    for(int f=0; f<FF; f++) h += sx[g][f]*W1[f*DD + d];
    d_h[r*DD + d] = h;
    float vi = h*ai1[d], vj = h*aj1[d];
    #pragma unroll
    for(int o=16;o>0;o>>=1){
        vi += __shfl_down_sync(0xffffffffu, vi, o);
        vj += __shfl_down_sync(0xffffffffu, vj, o);
    }
    if((t&31)==0){ svi[t>>5]=vi; svj[t>>5]=vj; }
    __syncthreads();
    if(d==0){
        d_si[r] = svi[2*g]+svi[2*g+1] + d_ei[r & (NN-1)];
        d_sj[r] = svj[2*g]+svj[2*g+1] + d_ej[r & (NN-1)];
    }
}

// ---------------- K4: layer-1 edge softmax + aggregation (4 rows/block) -----
__global__ void k_attn1(const float* __restrict__ bias1){
    int t = threadIdx.x;
    int g = t>>6, d = t&63;
    int r = blockIdx.x*4 + g;
    int b = r >> 7, i = r & (NN-1);
    __shared__ int   ssrc[4][TK];
    __shared__ float sal[4][TK];
    if(d < TK){
        int sn = d_topi1[i*TK + d];
        int s  = (b<<7) + sn;
        ssrc[g][d] = s;
        sal[g][d]  = lrelu(d_si[r] + d_sj[s]) * d_topv1[i*TK + d];
    }
    __syncthreads();
    if(d < 32){   // warp 2g does the softmax in parallel
        float v = (d < TK) ? sal[g][d] : -INFINITY;
        float m = v;
        #pragma unroll
        for(int o=16;o>0;o>>=1) m = fmaxf(m, __shfl_xor_sync(0xffffffffu, m, o));
        float e = (d < TK) ? expf(v - m) : 0.f;
        float s2 = e;
        #pragma unroll
        for(int o=16;o>0;o>>=1) s2 += __shfl_xor_sync(0xffffffffu, s2, o);
        if(d < TK) sal[g][d] = e / fmaxf(s2, 1e-12f);
    }
    __syncthreads();
    float a = 0.f;
    #pragma unroll
    for(int k=0;k<TK;k++) a += sal[g][k]*d_h[ssrc[g][k]*DD + d];
    d_agg[r*DD + d] = a + bias1[d];
}

// ---------------- batchnorm stats (two-pass, per channel) ----------------
__global__ void k_stats1(const float* __restrict__ gamma, const float* __restrict__ beta){
    int d = blockIdx.x, t = threadIdx.x;            // 256 threads
    __shared__ float sb[8];
    __shared__ float smu;
    float s = 0.f;
    for(int r=t; r<BNN; r+=256) s += d_agg[r*DD + d];
    #pragma unroll
    for(int o=16;o>0;o>>=1) s += __shfl_down_sync(0xffffffffu, s, o);
    if((t&31)==0) sb[t>>5] = s;
    __syncthreads();
    if(t==0){ float tot=0; for(int w=0;w<8;w++) tot+=sb[w]; smu = tot*(1.f/BNN); }
    __syncthreads();
    float mu = smu;
    float q = 0.f;
    for(int r=t; r<BNN; r+=256){ float x = d_agg[r*DD + d] - mu; q += x*x; }
    #pragma unroll
    for(int o=16;o>0;o>>=1) q += __shfl_down_sync(0xffffffffu, q, o);
    if((t&31)==0) sb[t>>5] = q;
    __syncthreads();
    if(t==0){
        float tot=0; for(int w=0;w<8;w++) tot+=sb[w];
        float var = tot*(1.f/BNN);
        float sc  = gamma[d]/sqrtf(var + 1e-5f);
        d_scale1[d] = sc; d_shift1[d] = beta[d] - mu*sc;
    }
}

__global__ void k_bnrelu(){
    int idx = blockIdx.x*256 + threadIdx.x;
    int d = idx & 63;
    d_g[idx] = fmaxf(d_scale1[d]*d_agg[idx] + d_shift1[d], 0.f);
}

// ---------------- K8: ef = P^T @ gcn (128-j tiles, cp.async, swap-fix) ------
#define EF_SMEM (64*128*4 + 64*64*4)   // A 32KB + B 16KB
__global__ void __launch_bounds__(128) k_ef(const float* __restrict__ P){
    extern __shared__ float efs[];
    float* As = efs;            // [64][128]  (P chunk, j-major, no transpose)
    float* Bs = efs + 64*128;   // [64][64]
    int t = threadIdx.x;
    int j0 = blockIdx.x*128;
    int slice = blockIdx.y;
    int tx = t & 7, ty = t >> 3;        // tx: d octet, ty: j octet
    int swb = (tx & 4) << 2;            // 0 or 16 bytes (conflict-free half swap)
    uint32_t sA = (uint32_t)__cvta_generic_to_shared(As);
    uint32_t sB = (uint32_t)__cvta_generic_to_shared(Bs);
    ull cp[8][4] = {};
    for(int cc=0; cc<8; cc++){
        int kb = slice*512 + cc*64;
        #pragma unroll
        for(int u=0; u<16; u++){
            int q = t + u*128; int row = q>>5, c16 = q&31;
            const float* src = &P[(size_t)(kb+row)*BNN + j0 + c16*4];
            asm volatile("cp.async.ca.shared.global [%0], [%1], 16;" ::
                "r"(sA + (uint32_t)((row*128 + c16*4)*4)), "l"(src));
        }
        #pragma unroll
        for(int u=0; u<8; u++){
            int q = t + u*128; int row = q>>4, c16 = q&15;
            const float* src = &d_g[(kb+row)*DD + c16*4];
            asm volatile("cp.async.ca.shared.global [%0], [%1], 16;" ::
                "r"(sB + (uint32_t)((row*64 + c16*4)*4)), "l"(src));
        }
        asm volatile("cp.async.commit_group;");
        asm volatile("cp.async.wait_group 0;");
        __syncthreads();
        #pragma unroll
        for(int k=0; k<64; k++){
            float4 a0 = *(float4*)&As[k*128 + ty*8];
            float4 a1 = *(float4*)&As[k*128 + ty*8 + 4];
            ulonglong2 bA = *(ulonglong2*)((char*)&Bs[k*64 + tx*8] + swb);
            ulonglong2 bB = *(ulonglong2*)((char*)&Bs[k*64 + tx*8] + (16 - swb));
            ull ra;
            ra=rep2(a0.x);
            cp[0][0]=ffma2(ra,bA.x,cp[0][0]); cp[0][1]=ffma2(ra,bA.y,cp[0][1]);
            cp[0][2]=ffma2(ra,bB.x,cp[0][2]); cp[0][3]=ffma2(ra,bB.y,cp[0][3]);
            ra=rep2(a0.y);
            cp[1][0]=ffma2(ra,bA.x,cp[1][0]); cp[1][1]=ffma2(ra,bA.y,cp[1][1]);
            cp[1][2]=ffma2(ra,bB.x,cp[1][2]); cp[1][3]=ffma2(ra,bB.y,cp[1][3]);
            ra=rep2(a0.z);
            cp[2][0]=ffma2(ra,bA.x,cp[2][0]); cp[2][1]=ffma2(ra,bA.y,cp[2][1]);
            cp[2][2]=ffma2(ra,bB.x,cp[2][2]); cp[2][3]=ffma2(ra,bB.y,cp[2][3]);
            ra=rep2(a0.w);
            cp[3][0]=ffma2(ra,bA.x,cp[3][0]); cp[3][1]=ffma2(ra,bA.y,cp[3][1]);
            cp[3][2]=ffma2(ra,bB.x,cp[3][2]); cp[3][3]=ffma2(ra,bB.y,cp[3][3]);
            ra=rep2(a1.x);
            cp[4][0]=ffma2(ra,bA.x,cp[4][0]); cp[4][1]=ffma2(ra,bA.y,cp[4][1]);
            cp[4][2]=ffma2(ra,bB.x,cp[4][2]); cp[4][3]=ffma2(ra,bB.y,cp[4][3]);
            ra=rep2(a1.y);
            cp[5][0]=ffma2(ra,bA.x,cp[5][0]); cp[5][1]=ffma2(ra,bA.y,cp[5][1]);
            cp[5][2]=ffma2(ra,bB.x,cp[5][2]); cp[5][3]=ffma2(ra,bB.y,cp[5][3]);
            ra=rep2(a1.z);
            cp[6][0]=ffma2(ra,bA.x,cp[6][0]); cp[6][1]=ffma2(ra,bA.y,cp[6][1]);
            cp[6][2]=ffma2(ra,bB.x,cp[6][2]); cp[6][3]=ffma2(ra,bB.y,cp[6][3]);
            ra=rep2(a1.w);
            cp[7][0]=ffma2(ra,bA.x,cp[7][0]); cp[7][1]=ffma2(ra,bA.y,cp[7][1]);
            cp[7][2]=ffma2(ra,bB.x,cp[7][2]); cp[7][3]=ffma2(ra,bB.y,cp[7][3]);
        }
        __syncthreads();
    }
    float* outp = &d_efp[(size_t)slice*BNN*DD];
    int cA = tx*8 + (swb>>2);
    int cB = tx*8 + 4 - (swb>>2);
    #pragma unroll
    for(int m=0;m<8;m++){
        int row = j0 + ty*8 + m;
        ulonglong2 o1; o1.x = cp[m][0]; o1.y = cp[m][1];
        ulonglong2 o2; o2.x = cp[m][2]; o2.y = cp[m][3];
        *(ulonglong2*)&outp[row*DD + cA] = o1;
        *(ulonglong2*)&outp[row*DD + cB] = o2;
    }
}

// ---------------- K9: row-normalize [gcn; ef] + zero CSR counters -----------
__global__ void k_gnorm(){
    int t = threadIdx.x;
    int gid = blockIdx.x*256 + t;
    if(gid < BNN){ d_cnt[gid] = 0; d_cur[gid] = 0; }
    int g = t>>6, d = t&63;
    int r = blockIdx.x*4 + g;
    __shared__ float sb[8];
    float v;
    if(r < BNN) v = d_g[r*DD + d];
    else {
        int rr = r - BNN;
        v = 0.f;
        #pragma unroll
        for(int s=0; s<NSLICE; s++) v += d_efp[(size_t)s*BNN*DD + rr*DD + d];
    }
    float ss = v*v;
    #pragma unroll
    for(int o=16;o>0;o>>=1) ss += __shfl_down_sync(0xffffffffu, ss, o);
    if((t&31)==0) sb[t>>5] = ss;
    __syncthreads();
    float inv = 1.f/fmaxf(sqrtf(sb[2*g]+sb[2*g+1]), 1e-12f);
    d_gn[r*DD + d] = v*inv;
}

// ---------------- K10: S = Gn[:BN] @ Gn^T (128x64 tiles, swap-fix) ----------
__global__ void __launch_bounds__(128) k_sgemm(){
    __shared__ float As[64][132];  // [d][m] m=128, transposed on load
    __shared__ float Bs[64][68];   // [d][n] n=64,  transposed on load
    int t = threadIdx.x;
    int j0 = blockIdx.x*64, i0 = blockIdx.y*128;
    #pragma unroll
    for(int u=0; u<16; u++){
        float4 va = *(const float4*)&d_gn[(i0+t)*DD + u*4];
        As[u*4+0][t]=va.x; As[u*4+1][t]=va.y; As[u*4+2][t]=va.z; As[u*4+3][t]=va.w;
    }
    #pragma unroll
    for(int u=0; u<8; u++){
        int f = t*8+u; int rr = f>>4; int cq = f&15;
        float4 vb = *(const float4*)&d_gn[(j0+rr)*DD + cq*4];
        Bs[cq*4+0][rr]=vb.x; Bs[cq*4+1][rr]=vb.y; Bs[cq*4+2][rr]=vb.z; Bs[cq*4+3][rr]=vb.w;
    }
    __syncthreads();
    int tx = t & 7, ty = t >> 3;   // tx: n octet, ty: m octet (16)
    int swb = (tx & 4) << 2;       // conflict-free half swap
    ull cp[8][4] = {};
    #pragma unroll
    for(int k=0; k<64; k++){
        float4 a0 = *(float4*)&As[k][ty*8];
        float4 a1 = *(float4*)&As[k][ty*8+4];
        ulonglong2 bA = *(ulonglong2*)((char*)&Bs[k][tx*8] + swb);
        ulonglong2 bB = *(ulonglong2*)((char*)&Bs[k][tx*8] + (16 - swb));
        ull ra;
        ra=rep2(a0.x);
        cp[0][0]=ffma2(ra,bA.x,cp[0][0]); cp[0][1]=ffma2(ra,bA.y,cp[0][1]);
        cp[0][2]=ffma2(ra,bB.x,cp[0][2]); cp[0][3]=ffma2(ra,bB.y,cp[0][3]);
        ra=rep2(a0.y);
        cp[1][0]=ffma2(ra,bA.x,cp[1][0]); cp[1][1]=ffma2(ra,bA.y,cp[1][1]);
        cp[1][2]=ffma2(ra,bB.x,cp[1][2]); cp[1][3]=ffma2(ra,bB.y,cp[1][3]);
        ra=rep2(a0.z);
        cp[2][0]=ffma2(ra,bA.x,cp[2][0]); cp[2][1]=ffma2(ra,bA.y,cp[2][1]);
        cp[2][2]=ffma2(ra,bB.x,cp[2][2]); cp[2][3]=ffma2(ra,bB.y,cp[2][3]);
        ra=rep2(a0.w);
        cp[3][0]=ffma2(ra,bA.x,cp[3][0]); cp[3][1]=ffma2(ra,bA.y,cp[3][1]);
        cp[3][2]=ffma2(ra,bB.x,cp[3][2]); cp[3][3]=ffma2(ra,bB.y,cp[3][3]);
        ra=rep2(a1.x);
        cp[4][0]=ffma2(ra,bA.x,cp[4][0]); cp[4][1]=ffma2(ra,bA.y,cp[4][1]);
        cp[4][2]=ffma2(ra,bB.x,cp[4][2]); cp[4][3]=ffma2(ra,bB.y,cp[4][3]);
        ra=rep2(a1.y);
        cp[5][0]=ffma2(ra,bA.x,cp[5][0]); cp[5][1]=ffma2(ra,bA.y,cp[5][1]);
        cp[5][2]=ffma2(ra,bB.x,cp[5][2]); cp[5][3]=ffma2(ra,bB.y,cp[5][3]);
        ra=rep2(a1.z);
        cp[6][0]=ffma2(ra,bA.x,cp[6][0]); cp[6][1]=ffma2(ra,bA.y,cp[6][1]);
        cp[6][2]=ffma2(ra,bB.x,cp[6][2]); cp[6][3]=ffma2(ra,bB.y,cp[6][3]);
        ra=rep2(a1.w);
        cp[7][0]=ffma2(ra,bA.x,cp[7][0]); cp[7][1]=ffma2(ra,bA.y,cp[7][1]);
        cp[7][2]=ffma2(ra,bB.x,cp[7][2]); cp[7][3]=ffma2(ra,bB.y,cp[7][3]);
    }
    int cA = j0 + tx*8 + (swb>>2);
    int cB = j0 + tx*8 + 4 - (swb>>2);
    #pragma unroll
    for(int m=0;m<8;m++){
        int row = i0 + ty*8 + m;
        ulonglong2 o1; o1.x = cp[m][0]; o1.y = cp[m][1];
        ulonglong2 o2; o2.x = cp[m][2]; o2.y = cp[m][3];
        *(ulonglong2*)&d_S[(size_t)row*G2 + cA] = o1;
        *(ulonglong2*)&d_S[(size_t)row*G2 + cB] = o2;
    }
}

// ---------------- K11: top-25 per row (register-resident, 1 bar/pick) -------
__global__ void k_top25(){
    int r = blockIdx.x, t = threadIdx.x;     // 256 threads
    float4 v[8];
    #pragma unroll
    for(int u=0; u<8; u++)
        v[u] = *(const float4*)&d_S[(size_t)r*G2 + (t + u*256)*4];
    unsigned rem = 0;
    float bv; int bi;
    #define RESCAN() do{ \
        bv = -INFINITY; bi = 0x7fffffff; \
        _Pragma("unroll") \
        for(int u=0;u<8;u++){ \
            int base = 4*(t + u*256); \
            float x0 = (rem&(1u<<(u*4+0))) ? -INFINITY : v[u].x; if(x0>bv){bv=x0;bi=base;} \
            float x1 = (rem&(1u<<(u*4+1))) ? -INFINITY : v[u].y; if(x1>bv){bv=x1;bi=base+1;} \
            float x2 = (rem&(1u<<(u*4+2))) ? -INFINITY : v[u].z; if(x2>bv){bv=x2;bi=base+2;} \
            float x3 = (rem&(1u<<(u*4+3))) ? -INFINITY : v[u].w; if(x3>bv){bv=x3;bi=base+3;} \
        } }while(0)
    RESCAN();
    __shared__ float swv[2][8];
    __shared__ int   swi[2][8];
    for(int it=0; it<EX; it++){
        float wv = bv; int wi = bi;
        #pragma unroll
        for(int o=16;o>0;o>>=1){
            float ov = __shfl_xor_sync(0xffffffffu, wv, o);
            int   oi = __shfl_xor_sync(0xffffffffu, wi, o);
            if(ov > wv || (ov == wv && oi < wi)){ wv = ov; wi = oi; }
        }
        int p = it & 1;
        if((t&31)==0){ swv[p][t>>5] = wv; swi[p][t>>5] = wi; }
        __syncthreads();
        float gm = swv[p][0]; int gi = swi[p][0];
        #pragma unroll
        for(int w=1;w<8;w++){
            if(swv[p][w] > gm || (swv[p][w] == gm && swi[p][w] < gi)){ gm = swv[p][w]; gi = swi[p][w]; }
        }
        if(t==0){
            d_topv2[r*EX+it] = gm;
            d_topi2[r*EX+it] = gi;
            if(gi < BNN) atomicAdd(&d_cnt[gi], 1);   // fused histogram
        }
        if(bi == gi){
            int q = gi >> 2;
            rem |= 1u << (((q >> 8) << 2) | (gi & 3));
            RESCAN();
        }
    }
    #undef RESCAN
}

// ---------------- K12: h2 = g[:BN] @ W2 + attention scalars (4 rows/blk) ----
__global__ void k_h2(const float* __restrict__ W2,
                     const float* __restrict__ ai2, const float* __restrict__ aj2){
    int t = threadIdx.x;
    int g = t>>6, d = t&63;
    int r = blockIdx.x*4 + g;
    __shared__ float sg[4][DD];
    __shared__ float svi[8], svj[8];
    sg[g][d] = d_g[r*DD + d];
    __syncthreads();
    float h = 0.f;
    #pragma unroll
    for(int k=0;k<DD;k++) h += sg[g][k]*W2[k*DD + d];
    d_h2[r*DD + d] = h;
    float vi = h*ai2[d], vj = h*aj2[d];
    #pragma unroll
    for(int o=16;o>0;o>>=1){
        vi += __shfl_down_sync(0xffffffffu, vi, o);
        vj += __shfl_down_sync(0xffffffffu, vj, o);
    }
    if((t&31)==0){ svi[t>>5]=vi; svj[t>>5]=vj; }
    __syncthreads();
    if(d==0){ d_hi2[r] = svi[2*g]+svi[2*g+1]; d_hj2[r] = svj[2*g]+svj[2*g+1]; }
}

// ---------------- K13/K14: CSR build (scan + scatter) -----------------------
__global__ void k_scan(){       // single block, 256 threads
    __shared__ int ss[256];
    int t = threadIdx.x;
    int c[16]; int s = 0;
    #pragma unroll
    for(int i=0;i<16;i++){ int x = d_cnt[t*16+i]; c[i] = s; s += x; }
    ss[t] = s;
    __syncthreads();
    for(int off=1; off<256; off<<=1){
        int v = (t>=off) ? ss[t-off] : 0;
        __syncthreads();
        ss[t] += v;
        __syncthreads();
    }
    int base = (t==0) ? 0 : ss[t-1];
    #pragma unroll
    for(int i=0;i<16;i++) d_off[t*16+i] = base + c[i];
    if(t==255) d_off[BNN] = ss[255];
}
__global__ void k_scatter(){
    int e = blockIdx.x*256 + threadIdx.x;
    int dst = d_topi2[e];
    if(dst < BNN){
        int p = atomicAdd(&d_cur[dst], 1);
        d_eid[d_off[dst] + p] = e;
    }
}

// ---------------- K15: fused segment softmax + gather + x3 ------------------
__global__ void k_seg(const float* __restrict__ bias2, const float* __restrict__ emb){
    int r = blockIdx.x, t = threadIdx.x;    // 64 threads
    int start = d_off[r], end = d_off[r+1];
    __shared__ float sred[2];
    __shared__ float sal[64];
    __shared__ int   ssrc[64];
    float hi = d_hi2[r];
    float m = -INFINITY;
    for(int e=start+t; e<end; e+=64){
        int eid = d_eid[e]; int src = eid/EX;
        float sc = lrelu(hi + d_hj2[src]) * d_topv2[eid];
        d_sc2[e] = sc;
        m = fmaxf(m, sc);
    }
    #pragma unroll
    for(int o=16;o>0;o>>=1) m = fmaxf(m, __shfl_down_sync(0xffffffffu, m, o));
    if((t&31)==0) sred[t>>5] = m;
    __syncthreads();
    m = fmaxf(sred[0], sred[1]);
    __syncthreads();
    float s = 0.f;
    for(int e=start+t; e<end; e+=64) s += expf(d_sc2[e]-m);
    #pragma unroll
    for(int o=16;o>0;o>>=1) s += __shfl_down_sync(0xffffffffu, s, o);
    if((t&31)==0) sred[t>>5] = s;
    __syncthreads();
    float inv = 1.f/fmaxf(sred[0]+sred[1], 1e-12f);
    float acc = 0.f;
    for(int c0=start; c0<end; c0+=64){
        __syncthreads();
        int e = c0 + t;
        if(e < end){
            int eid = d_eid[e];
            ssrc[t] = eid/EX;
            sal[t]  = expf(d_sc2[e]-m)*inv;
        }
        __syncthreads();
        int cnt = min(64, end - c0);
        for(int k=0;k<cnt;k++) acc += sal[k]*d_h2[ssrc[k]*DD + t];
    }
    // fused: x3 = relu(acc + bias2) * emb
    float x = fmaxf(acc + bias2[t], 0.f);
    d_x3[r*DD + t] = x * emb[(r & (NN-1))*DD + t];
}

__global__ void k_stats2(const float* __restrict__ gamma, const float* __restrict__ beta){
    int d = blockIdx.x, t = threadIdx.x;
    __shared__ float sb[8];
    __shared__ float smu;
    float s = 0.f;
    for(int r=t; r<BNN; r+=256) s += d_x3[r*DD + d];
    #pragma unroll
    for(int o=16;o>0;o>>=1) s += __shfl_down_sync(0xffffffffu, s, o);
    if((t&31)==0) sb[t>>5] = s;
    __syncthreads();
    if(t==0){ float tot=0; for(int w=0;w<8;w++) tot+=sb[w]; smu = tot*(1.f/BNN); }
    __syncthreads();
    float mu = smu;
    float q = 0.f;
    for(int r=t; r<BNN; r+=256){ float x = d_x3[r*DD + d] - mu; q += x*x; }
    #pragma unroll
    for(int o=16;o>0;o>>=1) q += __shfl_down_sync(0xffffffffu, q, o);
    if((t&31)==0) sb[t>>5] = q;
    __syncthreads();
    if(t==0){
        float tot=0; for(int w=0;w<8;w++) tot+=sb[w];
        float var = tot*(1.f/BNN);
        float sc  = gamma[d]/sqrtf(var + 1e-5f);
        d_scale2[d] = sc; d_shift2[d] = beta[d] - mu*sc;
    }
}

// ---------------- K17: output head (4 rows/block) ----------------
__global__ void k_out(const float* __restrict__ Wout, const float* __restrict__ bout,
                      float* __restrict__ out){
    int t = threadIdx.x;
    int g = t>>6, d = t&63;
    int r = blockIdx.x*4 + g;
    __shared__ float sb[8];
    float x = fmaxf(d_scale2[d]*d_x3[r*DD + d] + d_shift2[d], 0.f);
    float v = x * Wout[d];
    #pragma unroll
    for(int o=16;o>0;o>>=1) v += __shfl_down_sync(0xffffffffu, v, o);
    if((t&31)==0) sb[t>>5] = v;
    __syncthreads();
    if(d==0) out[r] = sb[2*g]+sb[2*g+1] + bout[0];
}

// ---------------- launch ----------------
extern "C" void kernel_launch(void* const* d_in, const int* in_sizes, int n_in,
                              void* d_out, int out_size){
    (void)in_sizes; (void)n_in; (void)out_size;
    const float* data  = (const float*)d_in[0];
    const float* emb   = (const float*)d_in[1];
    const float* W1    = (const float*)d_in[2];
    const float* ai1   = (const float*)d_in[3];
    const float* aj1   = (const float*)d_in[4];
    const float* bias1 = (const float*)d_in[5];
    const float* bn1g  = (const float*)d_in[6];
    const float* bn1b  = (const float*)d_in[7];
    const float* P     = (const float*)d_in[8];
    const float* W2    = (const float*)d_in[9];
    const float* ai2   = (const float*)d_in[10];
    const float* aj2   = (const float*)d_in[11];
    const float* bias2 = (const float*)d_in[12];
    const float* bnOg  = (const float*)d_in[13];
    const float* bnOb  = (const float*)d_in[14];
    const float* Wout  = (const float*)d_in[15];
    const float* bout  = (const float*)d_in[16];
    float* out = (float*)d_out;

    static int smem_set = 0;
    if(!smem_set){
        cudaFuncSetAttribute(k_ef, cudaFuncAttributeMaxDynamicSharedMemorySize, EF_SMEM);
        smem_set = 1;
    }

    k_embprep <<<NN, DD>>>(emb, ai1, aj1);
    k_cos1    <<<NN, NN>>>(emb);
    k_h       <<<BNN/4, 256>>>(data, W1, ai1, aj1);
    k_attn1   <<<BNN/4, 256>>>(bias1);
    k_stats1  <<<DD, 256>>>(bn1g, bn1b);
    k_bnrelu  <<<BNN*DD/256, 256>>>();
    k_ef      <<<dim3(32, NSLICE), 128, EF_SMEM>>>(P);
    k_gnorm   <<<G2/4, 256>>>();
    k_sgemm   <<<dim3(128, 32), 128>>>();
    k_top25   <<<BNN, 256>>>();
    k_h2      <<<BNN/4, 256>>>(W2, ai2, aj2);
    k_scan    <<<1, 256>>>();
    k_scatter <<<NE/256, 256>>>();
    k_seg     <<<BNN, 64>>>(bias2, emb);
    k_stats2  <<<DD, 256>>>(bnOg, bnOb);
    k_out     <<<BNN/4, 256>>>(Wout, bout, out);
}

// round 13
// speedup vs baseline: 1.7628x; 1.4337x over previous
#include <cuda_runtime.h>
#include <cuda_bf16.h>
#include <cstdint>
#include <math.h>

#define BB 32
#define NN 128
#define FF 10
#define DD 64
#define TK 20
#define EX 25
#define BNN 4096           // B*N
#define G2 8192            // 2*BN
#define NE (BNN*EX)        // 102400 candidate edges in layer 2
#define NSLICE 8

// ---------------- scratch (device globals: allocation-free) ----------------
__device__ float d_h[BNN*DD];
__device__ float d_si[BNN], d_sj[BNN];
__device__ float d_ei[NN], d_ej[NN], d_invn1[NN];
__device__ int   d_topi1[NN*TK];
__device__ float d_topv1[NN*TK];
__device__ float d_agg[BNN*DD];
__device__ float d_sum1[DD], d_ssq1[DD];
__device__ float d_sum2[DD], d_ssq2[DD];
__device__ float d_g[BNN*DD];               // gcn rows only
__device__ float d_efp[NSLICE*BNN*DD];      // ef partial sums per K-slice
__device__ float d_gn[G2*DD];               // row-normalized [gcn; ef]
__device__ float d_h2[BNN*DD];
__device__ float d_hi2[BNN], d_hj2[BNN];
__device__ float d_S[(size_t)BNN*G2];       // 128 MB cosine-score matrix
__device__ int   d_topi2[NE];
__device__ float d_topv2[NE];
__device__ int   d_cnt[BNN];
__device__ int   d_cur[BNN];
__device__ int   d_off[BNN+1];
__device__ int   d_eid[NE];
__device__ float d_sc2[NE];
__device__ float d_x3[BNN*DD];

// ---------------- helpers ----------------
__device__ __forceinline__ float lrelu(float x){ return x >= 0.f ? x : 0.2f*x; }

typedef unsigned long long ull;
__device__ __forceinline__ ull ffma2(ull a, ull b, ull c){
    ull d; asm("fma.rn.f32x2 %0, %1, %2, %3;" : "=l"(d) : "l"(a), "l"(b), "l"(c));
    return d;
}
__device__ __forceinline__ ull rep2(float x){
    ull d; asm("mov.b64 %0, {%1, %1};" : "=l"(d) : "r"(__float_as_uint(x)));
    return d;
}
__device__ __forceinline__ unsigned fenc(float v){
    unsigned u = __float_as_uint(v);
    return (u & 0x80000000u) ? ~u : (u | 0x80000000u);
}
__device__ __forceinline__ float fdec(unsigned k){
    return (k & 0x80000000u) ? __uint_as_float(k ^ 0x80000000u)
                             : __uint_as_float(~k);
}

// ---------------- K1: emb norms + attention key parts + accum zero ----------
__global__ void k_embprep(const float* __restrict__ emb,
                          const float* __restrict__ ai1,
                          const float* __restrict__ aj1){
    int n = blockIdx.x, t = threadIdx.x;
    if(n == 0){ d_sum1[t] = 0.f; d_ssq1[t] = 0.f; }
    float e  = emb[n*DD + t];
    float ss = e*e, vi = e*ai1[DD+t], vj = e*aj1[DD+t];
    __shared__ float sb[6];
    #pragma unroll
    for(int o=16;o>0;o>>=1){
        ss += __shfl_down_sync(0xffffffffu, ss, o);
        vi += __shfl_down_sync(0xffffffffu, vi, o);
        vj += __shfl_down_sync(0xffffffffu, vj, o);
    }
    if((t&31)==0){ int w=t>>5; sb[w]=ss; sb[2+w]=vi; sb[4+w]=vj; }
    __syncthreads();
    if(t==0){
        float nrm = sqrtf(sb[0]+sb[1]);
        d_invn1[n] = 1.f/fmaxf(nrm, 1e-12f);
        d_ei[n] = sb[2]+sb[3];
        d_ej[n] = sb[4]+sb[5];
    }
}

// ---------------- K2: cosine(emb,emb) + top-20 per node ----------------
__global__ void k_cos1(const float* __restrict__ emb){
    int i = blockIdx.x, t = threadIdx.x;            // 128 threads
    __shared__ float se[DD];
    __shared__ float sc[NN];
    __shared__ float rv[NN];
    __shared__ int   ridx[NN];
    if(t < DD) se[t] = emb[i*DD + t];
    __syncthreads();
    float dp = 0.f;
    #pragma unroll
    for(int d=0; d<DD; d++) dp += se[d]*emb[t*DD + d];
    sc[t] = dp * d_invn1[i] * d_invn1[t];
    __syncthreads();
    for(int it=0; it<TK; it++){
        rv[t] = sc[t]; ridx[t] = t;
        __syncthreads();
        for(int s=64; s>0; s>>=1){
            if(t < s){
                float v2 = rv[t+s]; int i2 = ridx[t+s];
                if(v2 > rv[t] || (v2 == rv[t] && i2 < ridx[t])){ rv[t]=v2; ridx[t]=i2; }
            }
            __syncthreads();
        }
        if(t==0){
            d_topv1[i*TK+it] = rv[0];
            d_topi1[i*TK+it] = ridx[0];
            sc[ridx[0]] = -INFINITY;
        }
        __syncthreads();
    }
}

// ---------------- K3: h = x@W1, si/sj scalars (4 rows/block) ----------------
__global__ void k_h(const float* __restrict__ data, const float* __restrict__ W1,
                    const float* __restrict__ ai1, const float* __restrict__ aj1){
    int t = threadIdx.x;
    int g = t>>6, d = t&63;
    int r = blockIdx.x*4 + g;
    __shared__ float sx[4][FF];
    __shared__ float svi[8], svj[8];
    if(d < FF) sx[g][d] = data[r*FF + d];
    __syncthreads();
    float h = 0.f;
    #pragma unroll
    for(int f=0; f<FF; f++) h += sx[g][f]*W1[f*DD + d];
    d_h[r*DD + d] = h;
    float vi = h*ai1[d], vj = h*aj1[d];
    #pragma unroll
    for(int o=16;o>0;o>>=1){
        vi += __shfl_down_sync(0xffffffffu, vi, o);
        vj += __shfl_down_sync(0xffffffffu, vj, o);
    }
    if((t&31)==0){ svi[t>>5]=vi; svj[t>>5]=vj; }
    __syncthreads();
    if(d==0){
        d_si[r] = svi[2*g]+svi[2*g+1] + d_ei[r & (NN-1)];
        d_sj[r] = svj[2*g]+svj[2*g+1] + d_ej[r & (NN-1)];
    }
}

// ---------------- K4: layer-1 softmax + aggregation + BN stats accum --------
__global__ void k_attn1(const float* __restrict__ bias1){
    int t = threadIdx.x;
    int g = t>>6, d = t&63;
    int r = blockIdx.x*4 + g;
    int b = r >> 7, i = r & (NN-1);
    __shared__ int   ssrc[4][TK];
    __shared__ float sal[4][TK];
    __shared__ float sa[256], sq[256];
    if(d < TK){
        int sn = d_topi1[i*TK + d];
        int s  = (b<<7) + sn;
        ssrc[g][d] = s;
        sal[g][d]  = lrelu(d_si[r] + d_sj[s]) * d_topv1[i*TK + d];
    }
    __syncthreads();
    if(d < 32){   // warp 2g does the softmax in parallel
        float v = (d < TK) ? sal[g][d] : -INFINITY;
        float m = v;
        #pragma unroll
        for(int o=16;o>0;o>>=1) m = fmaxf(m, __shfl_xor_sync(0xffffffffu, m, o));
        float e = (d < TK) ? expf(v - m) : 0.f;
        float s2 = e;
        #pragma unroll
        for(int o=16;o>0;o>>=1) s2 += __shfl_xor_sync(0xffffffffu, s2, o);
        if(d < TK) sal[g][d] = e / fmaxf(s2, 1e-12f);
    }
    __syncthreads();
    float a = 0.f;
    #pragma unroll
    for(int k=0;k<TK;k++) a += sal[g][k]*d_h[ssrc[g][k]*DD + d];
    a += bias1[d];
    d_agg[r*DD + d] = a;
    sa[t] = a; sq[t] = a*a;
    __syncthreads();
    if(t < DD){
        float s = sa[t]+sa[t+64]+sa[t+128]+sa[t+192];
        float q = sq[t]+sq[t+64]+sq[t+128]+sq[t+192];
        atomicAdd(&d_sum1[t], s);
        atomicAdd(&d_ssq1[t], q);
    }
}

// ---------------- K5: BN(relu) with inline stats ----------------
__global__ void k_bnrelu(const float* __restrict__ gamma, const float* __restrict__ beta){
    int idx = blockIdx.x*256 + threadIdx.x;
    int d = idx & 63;
    float mu  = d_sum1[d]*(1.f/BNN);
    float var = d_ssq1[d]*(1.f/BNN) - mu*mu;
    float sc  = gamma[d]/sqrtf(var + 1e-5f);
    float sh  = beta[d] - mu*sc;
    d_g[idx] = fmaxf(sc*d_agg[idx] + sh, 0.f);
}

// ---------------- K8: ef = P^T @ gcn (128-j tiles, cp.async, swap-fix) ------
#define EF_SMEM (64*128*4 + 64*64*4)   // A 32KB + B 16KB
__global__ void __launch_bounds__(128) k_ef(const float* __restrict__ P){
    extern __shared__ float efs[];
    float* As = efs;            // [64][128]
    float* Bs = efs + 64*128;   // [64][64]
    int t = threadIdx.x;
    int j0 = blockIdx.x*128;
    int slice = blockIdx.y;
    int tx = t & 7, ty = t >> 3;
    int swb = (tx & 4) << 2;
    uint32_t sA = (uint32_t)__cvta_generic_to_shared(As);
    uint32_t sB = (uint32_t)__cvta_generic_to_shared(Bs);
    ull cp[8][4] = {};
    for(int cc=0; cc<8; cc++){
        int kb = slice*512 + cc*64;
        #pragma unroll
        for(int u=0; u<16; u++){
            int q = t + u*128; int row = q>>5, c16 = q&31;
            const float* src = &P[(size_t)(kb+row)*BNN + j0 + c16*4];
            asm volatile("cp.async.ca.shared.global [%0], [%1], 16;" ::
                "r"(sA + (uint32_t)((row*128 + c16*4)*4)), "l"(src));
        }
        #pragma unroll
        for(int u=0; u<8; u++){
            int q = t + u*128; int row = q>>4, c16 = q&15;
            const float* src = &d_g[(kb+row)*DD + c16*4];
            asm volatile("cp.async.ca.shared.global [%0], [%1], 16;" ::
                "r"(sB + (uint32_t)((row*64 + c16*4)*4)), "l"(src));
        }
        asm volatile("cp.async.commit_group;");
        asm volatile("cp.async.wait_group 0;");
        __syncthreads();
        #pragma unroll
        for(int k=0; k<64; k++){
            float4 a0 = *(float4*)&As[k*128 + ty*8];
            float4 a1 = *(float4*)&As[k*128 + ty*8 + 4];
            ulonglong2 bA = *(ulonglong2*)((char*)&Bs[k*64 + tx*8] + swb);
            ulonglong2 bB = *(ulonglong2*)((char*)&Bs[k*64 + tx*8] + (16 - swb));
            ull ra;
            ra=rep2(a0.x);
            cp[0][0]=ffma2(ra,bA.x,cp[0][0]); cp[0][1]=ffma2(ra,bA.y,cp[0][1]);
            cp[0][2]=ffma2(ra,bB.x,cp[0][2]); cp[0][3]=ffma2(ra,bB.y,cp[0][3]);
            ra=rep2(a0.y);
            cp[1][0]=ffma2(ra,bA.x,cp[1][0]); cp[1][1]=ffma2(ra,bA.y,cp[1][1]);
            cp[1][2]=ffma2(ra,bB.x,cp[1][2]); cp[1][3]=ffma2(ra,bB.y,cp[1][3]);
            ra=rep2(a0.z);
            cp[2][0]=ffma2(ra,bA.x,cp[2][0]); cp[2][1]=ffma2(ra,bA.y,cp[2][1]);
            cp[2][2]=ffma2(ra,bB.x,cp[2][2]); cp[2][3]=ffma2(ra,bB.y,cp[2][3]);
            ra=rep2(a0.w);
            cp[3][0]=ffma2(ra,bA.x,cp[3][0]); cp[3][1]=ffma2(ra,bA.y,cp[3][1]);
            cp[3][2]=ffma2(ra,bB.x,cp[3][2]); cp[3][3]=ffma2(ra,bB.y,cp[3][3]);
            ra=rep2(a1.x);
            cp[4][0]=ffma2(ra,bA.x,cp[4][0]); cp[4][1]=ffma2(ra,bA.y,cp[4][1]);
            cp[4][2]=ffma2(ra,bB.x,cp[4][2]); cp[4][3]=ffma2(ra,bB.y,cp[4][3]);
            ra=rep2(a1.y);
            cp[5][0]=ffma2(ra,bA.x,cp[5][0]); cp[5][1]=ffma2(ra,bA.y,cp[5][1]);
            cp[5][2]=ffma2(ra,bB.x,cp[5][2]); cp[5][3]=ffma2(ra,bB.y,cp[5][3]);
            ra=rep2(a1.z);
            cp[6][0]=ffma2(ra,bA.x,cp[6][0]); cp[6][1]=ffma2(ra,bA.y,cp[6][1]);
            cp[6][2]=ffma2(ra,bB.x,cp[6][2]); cp[6][3]=ffma2(ra,bB.y,cp[6][3]);
            ra=rep2(a1.w);
            cp[7][0]=ffma2(ra,bA.x,cp[7][0]); cp[7][1]=ffma2(ra,bA.y,cp[7][1]);
            cp[7][2]=ffma2(ra,bB.x,cp[7][2]); cp[7][3]=ffma2(ra,bB.y,cp[7][3]);
        }
        __syncthreads();
    }
    float* outp = &d_efp[(size_t)slice*BNN*DD];
    int cA = tx*8 + (swb>>2);
    int cB = tx*8 + 4 - (swb>>2);
    #pragma unroll
    for(int m=0;m<8;m++){
        int row = j0 + ty*8 + m;
        ulonglong2 o1; o1.x = cp[m][0]; o1.y = cp[m][1];
        ulonglong2 o2; o2.x = cp[m][2]; o2.y = cp[m][3];
        *(ulonglong2*)&outp[row*DD + cA] = o1;
        *(ulonglong2*)&outp[row*DD + cB] = o2;
    }
}

// ---------------- K9: row-normalize [gcn; ef] + zero CSR counters -----------
__global__ void k_gnorm(){
    int t = threadIdx.x;
    int gid = blockIdx.x*256 + t;
    if(gid < BNN){ d_cnt[gid] = 0; d_cur[gid] = 0; }
    int g = t>>6, d = t&63;
    int r = blockIdx.x*4 + g;
    __shared__ float sb[8];
    float v;
    if(r < BNN) v = d_g[r*DD + d];
    else {
        int rr = r - BNN;
        v = 0.f;
        #pragma unroll
        for(int s=0; s<NSLICE; s++) v += d_efp[(size_t)s*BNN*DD + rr*DD + d];
    }
    float ss = v*v;
    #pragma unroll
    for(int o=16;o>0;o>>=1) ss += __shfl_down_sync(0xffffffffu, ss, o);
    if((t&31)==0) sb[t>>5] = ss;
    __syncthreads();
    float inv = 1.f/fmaxf(sqrtf(sb[2*g]+sb[2*g+1]), 1e-12f);
    d_gn[r*DD + d] = v*inv;
}

// ---------------- K10: S = Gn[:BN] @ Gn^T (128x64 tiles, swap-fix) ----------
__global__ void __launch_bounds__(128) k_sgemm(){
    __shared__ float As[64][132];
    __shared__ float Bs[64][68];
    int t = threadIdx.x;
    int j0 = blockIdx.x*64, i0 = blockIdx.y*128;
    #pragma unroll
    for(int u=0; u<16; u++){
        float4 va = *(const float4*)&d_gn[(i0+t)*DD + u*4];
        As[u*4+0][t]=va.x; As[u*4+1][t]=va.y; As[u*4+2][t]=va.z; As[u*4+3][t]=va.w;
    }
    #pragma unroll
    for(int u=0; u<8; u++){
        int f = t*8+u; int rr = f>>4; int cq = f&15;
        float4 vb = *(const float4*)&d_gn[(j0+rr)*DD + cq*4];
        Bs[cq*4+0][rr]=vb.x; Bs[cq*4+1][rr]=vb.y; Bs[cq*4+2][rr]=vb.z; Bs[cq*4+3][rr]=vb.w;
    }
    __syncthreads();
    int tx = t & 7, ty = t >> 3;
    int swb = (tx & 4) << 2;
    ull cp[8][4] = {};
    #pragma unroll
    for(int k=0; k<64; k++){
        float4 a0 = *(float4*)&As[k][ty*8];
        float4 a1 = *(float4*)&As[k][ty*8+4];
        ulonglong2 bA = *(ulonglong2*)((char*)&Bs[k][tx*8] + swb);
        ulonglong2 bB = *(ulonglong2*)((char*)&Bs[k][tx*8] + (16 - swb));
        ull ra;
        ra=rep2(a0.x);
        cp[0][0]=ffma2(ra,bA.x,cp[0][0]); cp[0][1]=ffma2(ra,bA.y,cp[0][1]);
        cp[0][2]=ffma2(ra,bB.x,cp[0][2]); cp[0][3]=ffma2(ra,bB.y,cp[0][3]);
        ra=rep2(a0.y);
        cp[1][0]=ffma2(ra,bA.x,cp[1][0]); cp[1][1]=ffma2(ra,bA.y,cp[1][1]);
        cp[1][2]=ffma2(ra,bB.x,cp[1][2]); cp[1][3]=ffma2(ra,bB.y,cp[1][3]);
        ra=rep2(a0.z);
        cp[2][0]=ffma2(ra,bA.x,cp[2][0]); cp[2][1]=ffma2(ra,bA.y,cp[2][1]);
        cp[2][2]=ffma2(ra,bB.x,cp[2][2]); cp[2][3]=ffma2(ra,bB.y,cp[2][3]);
        ra=rep2(a0.w);
        cp[3][0]=ffma2(ra,bA.x,cp[3][0]); cp[3][1]=ffma2(ra,bA.y,cp[3][1]);
        cp[3][2]=ffma2(ra,bB.x,cp[3][2]); cp[3][3]=ffma2(ra,bB.y,cp[3][3]);
        ra=rep2(a1.x);
        cp[4][0]=ffma2(ra,bA.x,cp[4][0]); cp[4][1]=ffma2(ra,bA.y,cp[4][1]);
        cp[4][2]=ffma2(ra,bB.x,cp[4][2]); cp[4][3]=ffma2(ra,bB.y,cp[4][3]);
        ra=rep2(a1.y);
        cp[5][0]=ffma2(ra,bA.x,cp[5][0]); cp[5][1]=ffma2(ra,bA.y,cp[5][1]);
        cp[5][2]=ffma2(ra,bB.x,cp[5][2]); cp[5][3]=ffma2(ra,bB.y,cp[5][3]);
        ra=rep2(a1.z);
        cp[6][0]=ffma2(ra,bA.x,cp[6][0]); cp[6][1]=ffma2(ra,bA.y,cp[6][1]);
        cp[6][2]=ffma2(ra,bB.x,cp[6][2]); cp[6][3]=ffma2(ra,bB.y,cp[6][3]);
        ra=rep2(a1.w);
        cp[7][0]=ffma2(ra,bA.x,cp[7][0]); cp[7][1]=ffma2(ra,bA.y,cp[7][1]);
        cp[7][2]=ffma2(ra,bB.x,cp[7][2]); cp[7][3]=ffma2(ra,bB.y,cp[7][3]);
    }
    int cA = j0 + tx*8 + (swb>>2);
    int cB = j0 + tx*8 + 4 - (swb>>2);
    #pragma unroll
    for(int m=0;m<8;m++){
        int row = i0 + ty*8 + m;
        ulonglong2 o1; o1.x = cp[m][0]; o1.y = cp[m][1];
        ulonglong2 o2; o2.x = cp[m][2]; o2.y = cp[m][3];
        *(ulonglong2*)&d_S[(size_t)row*G2 + cA] = o1;
        *(ulonglong2*)&d_S[(size_t)row*G2 + cB] = o2;
    }
}

// ---------------- K11: top-25 per row via exact 4-round radix select --------
__global__ void k_top25(){
    int r = blockIdx.x, t = threadIdx.x;     // 256 threads
    unsigned e[32];
    #pragma unroll
    for(int u=0; u<8; u++){
        float4 f = *(const float4*)&d_S[(size_t)r*G2 + (t + u*256)*4];
        e[u*4+0] = fenc(f.x); e[u*4+1] = fenc(f.y);
        e[u*4+2] = fenc(f.z); e[u*4+3] = fenc(f.w);
    }
    __shared__ unsigned hist[256];
    __shared__ unsigned spref;
    __shared__ int sneed, epos, eqn;
    __shared__ int eqlist[64];
    if(t==0){ spref=0u; sneed=EX; epos=0; eqn=0; }
    for(int round=0; round<4; round++){
        hist[t] = 0;
        __syncthreads();
        unsigned pref = spref;
        int shift = 24 - 8*round;
        if(round==0){
            #pragma unroll
            for(int u=0;u<32;u++) atomicAdd(&hist[e[u]>>24], 1u);
        } else {
            int hshift = shift + 8;
            #pragma unroll
            for(int u=0;u<32;u++)
                if((e[u]>>hshift) == pref) atomicAdd(&hist[(e[u]>>shift)&255u], 1u);
        }
        __syncthreads();
        if(t < 32){
            int need = sneed;
            unsigned hv[8]; unsigned p0 = 0;
            #pragma unroll
            for(int q=0;q<8;q++){ hv[q]=hist[t*8+q]; p0+=hv[q]; }
            unsigned s = p0;
            #pragma unroll
            for(int o=1;o<32;o<<=1){
                unsigned vv = __shfl_down_sync(0xffffffffu, s, o);
                if(t+o < 32) s += vv;
            }
            unsigned cum = s - p0;              // count of values in higher lanes
            #pragma unroll
            for(int q=7;q>=0;q--){
                unsigned nc = cum + hv[q];
                if(cum < (unsigned)need && nc >= (unsigned)need){
                    spref = (pref<<8) | (unsigned)(t*8+q);
                    sneed = need - (int)cum;
                }
                cum = nc;
            }
        }
        __syncthreads();
    }
    unsigned T = spref; int needEq = sneed;
    #pragma unroll
    for(int u=0; u<8; u++){
        #pragma unroll
        for(int j=0; j<4; j++){
            unsigned ev = e[u*4+j];
            if(ev >= T){
                int idx = (t + u*256)*4 + j;
                if(ev > T){
                    int p = atomicAdd(&epos, 1);
                    d_topv2[r*EX+p] = fdec(ev);
                    d_topi2[r*EX+p] = idx;
                    if(idx < BNN) atomicAdd(&d_cnt[idx], 1);
                } else {
                    int q = atomicAdd(&eqn, 1);
                    if(q < 64) eqlist[q] = idx;
                }
            }
        }
    }
    __syncthreads();
    if(t==0){
        int base = epos;                 // == EX - needEq
        int n = eqn < 64 ? eqn : 64;
        for(int s2=0; s2<needEq; s2++){
            int bi = 0x7fffffff, bq = 0;
            for(int q=0; q<n; q++) if(eqlist[q] < bi){ bi = eqlist[q]; bq = q; }
            eqlist[bq] = 0x7fffffff;
            d_topv2[r*EX+base+s2] = fdec(T);
            d_topi2[r*EX+base+s2] = bi;
            if(bi < BNN) atomicAdd(&d_cnt[bi], 1);
        }
    }
}

// ---------------- K12: h2 = g[:BN] @ W2 + attention scalars (4 rows/blk) ----
__global__ void k_h2(const float* __restrict__ W2,
                     const float* __restrict__ ai2, const float* __restrict__ aj2){
    int t = threadIdx.x;
    int g = t>>6, d = t&63;
    int r = blockIdx.x*4 + g;
    __shared__ float sg[4][DD];
    __shared__ float svi[8], svj[8];
    sg[g][d] = d_g[r*DD + d];
    __syncthreads();
    float h = 0.f;
    #pragma unroll
    for(int k=0;k<DD;k++) h += sg[g][k]*W2[k*DD + d];
    d_h2[r*DD + d] = h;
    float vi = h*ai2[d], vj = h*aj2[d];
    #pragma unroll
    for(int o=16;o>0;o>>=1){
        vi += __shfl_down_sync(0xffffffffu, vi, o);
        vj += __shfl_down_sync(0xffffffffu, vj, o);
    }
    if((t&31)==0){ svi[t>>5]=vi; svj[t>>5]=vj; }
    __syncthreads();
    if(d==0){ d_hi2[r] = svi[2*g]+svi[2*g+1]; d_hj2[r] = svj[2*g]+svj[2*g+1]; }
}

// ---------------- K13/K14: CSR build (scan + scatter) -----------------------
__global__ void k_scan(){       // single block, 256 threads
    __shared__ int ss[256];
    int t = threadIdx.x;
    if(t < DD){ d_sum2[t] = 0.f; d_ssq2[t] = 0.f; }
    int c[16]; int s = 0;
    #pragma unroll
    for(int i=0;i<16;i++){ int x = d_cnt[t*16+i]; c[i] = s; s += x; }
    ss[t] = s;
    __syncthreads();
    for(int off=1; off<256; off<<=1){
        int v = (t>=off) ? ss[t-off] : 0;
        __syncthreads();
        ss[t] += v;
        __syncthreads();
    }
    int base = (t==0) ? 0 : ss[t-1];
    #pragma unroll
    for(int i=0;i<16;i++) d_off[t*16+i] = base + c[i];
    if(t==255) d_off[BNN] = ss[255];
}
__global__ void k_scatter(){
    int e = blockIdx.x*256 + threadIdx.x;
    int dst = d_topi2[e];
    if(dst < BNN){
        int p = atomicAdd(&d_cur[dst], 1);
        d_eid[d_off[dst] + p] = e;
    }
}

// ---------------- K15: segment softmax + gather + x3 + BN stats accum -------
__global__ void k_seg(const float* __restrict__ bias2, const float* __restrict__ emb){
    int r = blockIdx.x, t = threadIdx.x;    // 64 threads
    int start = d_off[r], end = d_off[r+1];
    __shared__ float sred[2];
    __shared__ float sal[64];
    __shared__ int   ssrc[64];
    float hi = d_hi2[r];
    float m = -INFINITY;
    for(int e=start+t; e<end; e+=64){
        int eid = d_eid[e]; int src = eid/EX;
        float sc = lrelu(hi + d_hj2[src]) * d_topv2[eid];
        d_sc2[e] = sc;
        m = fmaxf(m, sc);
    }
    #pragma unroll
    for(int o=16;o>0;o>>=1) m = fmaxf(m, __shfl_down_sync(0xffffffffu, m, o));
    if((t&31)==0) sred[t>>5] = m;
    __syncthreads();
    m = fmaxf(sred[0], sred[1]);
    __syncthreads();
    float s = 0.f;
    for(int e=start+t; e<end; e+=64) s += expf(d_sc2[e]-m);
    #pragma unroll
    for(int o=16;o>0;o>>=1) s += __shfl_down_sync(0xffffffffu, s, o);
    if((t&31)==0) sred[t>>5] = s;
    __syncthreads();
    float inv = 1.f/fmaxf(sred[0]+sred[1], 1e-12f);
    float acc = 0.f;
    for(int c0=start; c0<end; c0+=64){
        __syncthreads();
        int e = c0 + t;
        if(e < end){
            int eid = d_eid[e];
            ssrc[t] = eid/EX;
            sal[t]  = expf(d_sc2[e]-m)*inv;
        }
        __syncthreads();
        int cnt = min(64, end - c0);
        for(int k=0;k<cnt;k++) acc += sal[k]*d_h2[ssrc[k]*DD + t];
    }
    float x = fmaxf(acc + bias2[t], 0.f);
    float x3v = x * emb[(r & (NN-1))*DD + t];
    d_x3[r*DD + t] = x3v;
    atomicAdd(&d_sum2[t], x3v);
    atomicAdd(&d_ssq2[t], x3v*x3v);
}

// ---------------- K17: output head (4 rows/block, inline BN) ----------------
__global__ void k_out(const float* __restrict__ gamma, const float* __restrict__ beta,
                      const float* __restrict__ Wout, const float* __restrict__ bout,
                      float* __restrict__ out){
    int t = threadIdx.x;
    int g = t>>6, d = t&63;
    int r = blockIdx.x*4 + g;
    __shared__ float sb[8];
    float mu  = d_sum2[d]*(1.f/BNN);
    float var = d_ssq2[d]*(1.f/BNN) - mu*mu;
    float sc  = gamma[d]/sqrtf(var + 1e-5f);
    float sh  = beta[d] - mu*sc;
    float x = fmaxf(sc*d_x3[r*DD + d] + sh, 0.f);
    float v = x * Wout[d];
    #pragma unroll
    for(int o=16;o>0;o>>=1) v += __shfl_down_sync(0xffffffffu, v, o);
    if((t&31)==0) sb[t>>5] = v;
    __syncthreads();
    if(d==0) out[r] = sb[2*g]+sb[2*g+1] + bout[0];
}

// ---------------- launch ----------------
extern "C" void kernel_launch(void* const* d_in, const int* in_sizes, int n_in,
                              void* d_out, int out_size){
    (void)in_sizes; (void)n_in; (void)out_size;
    const float* data  = (const float*)d_in[0];
    const float* emb   = (const float*)d_in[1];
    const float* W1    = (const float*)d_in[2];
    const float* ai1   = (const float*)d_in[3];
    const float* aj1   = (const float*)d_in[4];
    const float* bias1 = (const float*)d_in[5];
    const float* bn1g  = (const float*)d_in[6];
    const float* bn1b  = (const float*)d_in[7];
    const float* P     = (const float*)d_in[8];
    const float* W2    = (const float*)d_in[9];
    const float* ai2   = (const float*)d_in[10];
    const float* aj2   = (const float*)d_in[11];
    const float* bias2 = (const float*)d_in[12];
    const float* bnOg  = (const float*)d_in[13];
    const float* bnOb  = (const float*)d_in[14];
    const float* Wout  = (const float*)d_in[15];
    const float* bout  = (const float*)d_in[16];
    float* out = (float*)d_out;

    static int smem_set = 0;
    if(!smem_set){
        cudaFuncSetAttribute(k_ef, cudaFuncAttributeMaxDynamicSharedMemorySize, EF_SMEM);
        smem_set = 1;
    }

    k_embprep <<<NN, DD>>>(emb, ai1, aj1);
    k_cos1    <<<NN, NN>>>(emb);
    k_h       <<<BNN/4, 256>>>(data, W1, ai1, aj1);
    k_attn1   <<<BNN/4, 256>>>(bias1);
    k_bnrelu  <<<BNN*DD/256, 256>>>(bn1g, bn1b);
    k_ef      <<<dim3(32, NSLICE), 128, EF_SMEM>>>(P);
    k_gnorm   <<<G2/4, 256>>>();
    k_sgemm   <<<dim3(128, 32), 128>>>();
    k_top25   <<<BNN, 256>>>();
    k_h2      <<<BNN/4, 256>>>(W2, ai2, aj2);
    k_scan    <<<1, 256>>>();
    k_scatter <<<NE/256, 256>>>();
    k_seg     <<<BNN, 64>>>(bias2, emb);
    k_out     <<<BNN/4, 256>>>(bnOg, bnOb, Wout, bout, out);
}

// round 14
// speedup vs baseline: 1.7955x; 1.0185x over previous
#include <cuda_runtime.h>
#include <cuda_bf16.h>
#include <cstdint>
#include <math.h>

#define BB 32
#define NN 128
#define FF 10
#define DD 64
#define TK 20
#define EX 25
#define BNN 4096           // B*N
#define G2 8192            // 2*BN
#define NE (BNN*EX)        // 102400 candidate edges in layer 2
#define NSLICE 8

// ---------------- scratch (device globals: allocation-free) ----------------
__device__ float d_h[BNN*DD];
__device__ float d_si[BNN], d_sj[BNN];
__device__ float d_ei[NN], d_ej[NN], d_invn1[NN];
__device__ int   d_topi1[NN*TK];
__device__ float d_topv1[NN*TK];
__device__ float d_agg[BNN*DD];
__device__ float d_sum1[DD], d_ssq1[DD];
__device__ float d_sum2[DD], d_ssq2[DD];
__device__ float d_g[BNN*DD];               // gcn rows only
__device__ float d_efp[NSLICE*BNN*DD];      // ef partial sums per K-slice
__device__ float d_gn[G2*DD];               // row-normalized [gcn; ef]
__device__ float d_h2[BNN*DD];
__device__ float d_hi2[BNN], d_hj2[BNN];
__device__ float d_S[(size_t)BNN*G2];       // 128 MB cosine-score matrix
__device__ int   d_topi2[NE];
__device__ float d_topv2[NE];
__device__ int   d_cnt[BNN];
__device__ int   d_cur[BNN];
__device__ int   d_off[BNN+1];
__device__ int   d_eid[NE];
__device__ float d_sc2[NE];
__device__ float d_x3[BNN*DD];

// ---------------- helpers ----------------
__device__ __forceinline__ float lrelu(float x){ return x >= 0.f ? x : 0.2f*x; }

typedef unsigned long long ull;
__device__ __forceinline__ ull ffma2(ull a, ull b, ull c){
    ull d; asm("fma.rn.f32x2 %0, %1, %2, %3;" : "=l"(d) : "l"(a), "l"(b), "l"(c));
    return d;
}
__device__ __forceinline__ ull rep2(float x){
    ull d; asm("mov.b64 %0, {%1, %1};" : "=l"(d) : "r"(__float_as_uint(x)));
    return d;
}
__device__ __forceinline__ unsigned fenc(float v){
    unsigned u = __float_as_uint(v);
    return (u & 0x80000000u) ? ~u : (u | 0x80000000u);
}
__device__ __forceinline__ float fdec(unsigned k){
    return (k & 0x80000000u) ? __uint_as_float(k ^ 0x80000000u)
                             : __uint_as_float(~k);
}

// ---------------- K1: emb norms + attention key parts + accum zero ----------
__global__ void k_embprep(const float* __restrict__ emb,
                          const float* __restrict__ ai1,
                          const float* __restrict__ aj1){
    int n = blockIdx.x, t = threadIdx.x;
    if(n == 0){ d_sum1[t] = 0.f; d_ssq1[t] = 0.f; }
    float e  = emb[n*DD + t];
    float ss = e*e, vi = e*ai1[DD+t], vj = e*aj1[DD+t];
    __shared__ float sb[6];
    #pragma unroll
    for(int o=16;o>0;o>>=1){
        ss += __shfl_down_sync(0xffffffffu, ss, o);
        vi += __shfl_down_sync(0xffffffffu, vi, o);
        vj += __shfl_down_sync(0xffffffffu, vj, o);
    }
    if((t&31)==0){ int w=t>>5; sb[w]=ss; sb[2+w]=vi; sb[4+w]=vj; }
    __syncthreads();
    if(t==0){
        float nrm = sqrtf(sb[0]+sb[1]);
        d_invn1[n] = 1.f/fmaxf(nrm, 1e-12f);
        d_ei[n] = sb[2]+sb[3];
        d_ej[n] = sb[4]+sb[5];
    }
}

// ---------------- K2: cosine(emb,emb) + top-20 per node ----------------
__global__ void k_cos1(const float* __restrict__ emb){
    int i = blockIdx.x, t = threadIdx.x;            // 128 threads
    __shared__ float se[DD];
    __shared__ float sc[NN];
    __shared__ float rv[NN];
    __shared__ int   ridx[NN];
    if(t < DD) se[t] = emb[i*DD + t];
    __syncthreads();
    float dp = 0.f;
    #pragma unroll
    for(int d=0; d<DD; d++) dp += se[d]*emb[t*DD + d];
    sc[t] = dp * d_invn1[i] * d_invn1[t];
    __syncthreads();
    for(int it=0; it<TK; it++){
        rv[t] = sc[t]; ridx[t] = t;
        __syncthreads();
        for(int s=64; s>0; s>>=1){
            if(t < s){
                float v2 = rv[t+s]; int i2 = ridx[t+s];
                if(v2 > rv[t] || (v2 == rv[t] && i2 < ridx[t])){ rv[t]=v2; ridx[t]=i2; }
            }
            __syncthreads();
        }
        if(t==0){
            d_topv1[i*TK+it] = rv[0];
            d_topi1[i*TK+it] = ridx[0];
            sc[ridx[0]] = -INFINITY;
        }
        __syncthreads();
    }
}

// ---------------- K3: h = x@W1, si/sj scalars (4 rows/block) ----------------
__global__ void k_h(const float* __restrict__ data, const float* __restrict__ W1,
                    const float* __restrict__ ai1, const float* __restrict__ aj1){
    int t = threadIdx.x;
    int g = t>>6, d = t&63;
    int r = blockIdx.x*4 + g;
    __shared__ float sx[4][FF];
    __shared__ float svi[8], svj[8];
    if(d < FF) sx[g][d] = data[r*FF + d];
    __syncthreads();
    float h = 0.f;
    #pragma unroll
    for(int f=0; f<FF; f++) h += sx[g][f]*W1[f*DD + d];
    d_h[r*DD + d] = h;
    float vi = h*ai1[d], vj = h*aj1[d];
    #pragma unroll
    for(int o=16;o>0;o>>=1){
        vi += __shfl_down_sync(0xffffffffu, vi, o);
        vj += __shfl_down_sync(0xffffffffu, vj, o);
    }
    if((t&31)==0){ svi[t>>5]=vi; svj[t>>5]=vj; }
    __syncthreads();
    if(d==0){
        d_si[r] = svi[2*g]+svi[2*g+1] + d_ei[r & (NN-1)];
        d_sj[r] = svj[2*g]+svj[2*g+1] + d_ej[r & (NN-1)];
    }
}

// ---------------- K4: layer-1 softmax + aggregation + BN stats accum --------
__global__ void k_attn1(const float* __restrict__ bias1){
    int t = threadIdx.x;
    int g = t>>6, d = t&63;
    int r = blockIdx.x*4 + g;
    int b = r >> 7, i = r & (NN-1);
    __shared__ int   ssrc[4][TK];
    __shared__ float sal[4][TK];
    __shared__ float sa[256], sq[256];
    if(d < TK){
        int sn = d_topi1[i*TK + d];
        int s  = (b<<7) + sn;
        ssrc[g][d] = s;
        sal[g][d]  = lrelu(d_si[r] + d_sj[s]) * d_topv1[i*TK + d];
    }
    __syncthreads();
    if(d < 32){   // warp 2g does the softmax in parallel
        float v = (d < TK) ? sal[g][d] : -INFINITY;
        float m = v;
        #pragma unroll
        for(int o=16;o>0;o>>=1) m = fmaxf(m, __shfl_xor_sync(0xffffffffu, m, o));
        float e = (d < TK) ? expf(v - m) : 0.f;
        float s2 = e;
        #pragma unroll
        for(int o=16;o>0;o>>=1) s2 += __shfl_xor_sync(0xffffffffu, s2, o);
        if(d < TK) sal[g][d] = e / fmaxf(s2, 1e-12f);
    }
    __syncthreads();
    float a = 0.f;
    #pragma unroll
    for(int k=0;k<TK;k++) a += sal[g][k]*d_h[ssrc[g][k]*DD + d];
    a += bias1[d];
    d_agg[r*DD + d] = a;
    sa[t] = a; sq[t] = a*a;
    __syncthreads();
    if(t < DD){
        float s = sa[t]+sa[t+64]+sa[t+128]+sa[t+192];
        float q = sq[t]+sq[t+64]+sq[t+128]+sq[t+192];
        atomicAdd(&d_sum1[t], s);
        atomicAdd(&d_ssq1[t], q);
    }
}

// ---------------- K5: BN(relu) with inline stats ----------------
__global__ void k_bnrelu(const float* __restrict__ gamma, const float* __restrict__ beta){
    int idx = blockIdx.x*256 + threadIdx.x;
    int d = idx & 63;
    float mu  = d_sum1[d]*(1.f/BNN);
    float var = d_ssq1[d]*(1.f/BNN) - mu*mu;
    float sc  = gamma[d]/sqrtf(var + 1e-5f);
    float sh  = beta[d] - mu*sc;
    d_g[idx] = fmaxf(sc*d_agg[idx] + sh, 0.f);
}

// ---------------- K8: ef = P^T @ gcn (double-buffered cp.async) -------------
#define EF_BUF (64*128 + 64*64)
#define EF_SMEM (2*EF_BUF*4)   // 96 KB
__global__ void __launch_bounds__(128) k_ef(const float* __restrict__ P){
    extern __shared__ float efs[];
    int t = threadIdx.x;
    int j0 = blockIdx.x*128;
    int slice = blockIdx.y;
    int tx = t & 7, ty = t >> 3;
    int swb = (tx & 4) << 2;
    ull cp[8][4] = {};

    // stage chunk cc into buffer buf
    auto stage = [&](int cc, int buf){
        int kb = slice*512 + cc*64;
        uint32_t sA = (uint32_t)__cvta_generic_to_shared(efs + buf*EF_BUF);
        uint32_t sB = sA + 64*128*4;
        #pragma unroll
        for(int u=0; u<16; u++){
            int q = t + u*128; int row = q>>5, c16 = q&31;
            const float* src = &P[(size_t)(kb+row)*BNN + j0 + c16*4];
            asm volatile("cp.async.ca.shared.global [%0], [%1], 16;" ::
                "r"(sA + (uint32_t)((row*128 + c16*4)*4)), "l"(src));
        }
        #pragma unroll
        for(int u=0; u<8; u++){
            int q = t + u*128; int row = q>>4, c16 = q&15;
            const float* src = &d_g[(kb+row)*DD + c16*4];
            asm volatile("cp.async.ca.shared.global [%0], [%1], 16;" ::
                "r"(sB + (uint32_t)((row*64 + c16*4)*4)), "l"(src));
        }
        asm volatile("cp.async.commit_group;");
    };

    stage(0, 0);
    for(int cc=0; cc<8; cc++){
        if(cc < 7) stage(cc+1, (cc+1)&1);
        if(cc < 7) asm volatile("cp.async.wait_group 1;");
        else       asm volatile("cp.async.wait_group 0;");
        __syncthreads();
        float* As = efs + (cc&1)*EF_BUF;
        float* Bs = As + 64*128;
        #pragma unroll
        for(int k=0; k<64; k++){
            float4 a0 = *(float4*)&As[k*128 + ty*8];
            float4 a1 = *(float4*)&As[k*128 + ty*8 + 4];
            ulonglong2 bA = *(ulonglong2*)((char*)&Bs[k*64 + tx*8] + swb);
            ulonglong2 bB = *(ulonglong2*)((char*)&Bs[k*64 + tx*8] + (16 - swb));
            ull ra;
            ra=rep2(a0.x);
            cp[0][0]=ffma2(ra,bA.x,cp[0][0]); cp[0][1]=ffma2(ra,bA.y,cp[0][1]);
            cp[0][2]=ffma2(ra,bB.x,cp[0][2]); cp[0][3]=ffma2(ra,bB.y,cp[0][3]);
            ra=rep2(a0.y);
            cp[1][0]=ffma2(ra,bA.x,cp[1][0]); cp[1][1]=ffma2(ra,bA.y,cp[1][1]);
            cp[1][2]=ffma2(ra,bB.x,cp[1][2]); cp[1][3]=ffma2(ra,bB.y,cp[1][3]);
            ra=rep2(a0.z);
            cp[2][0]=ffma2(ra,bA.x,cp[2][0]); cp[2][1]=ffma2(ra,bA.y,cp[2][1]);
            cp[2][2]=ffma2(ra,bB.x,cp[2][2]); cp[2][3]=ffma2(ra,bB.y,cp[2][3]);
            ra=rep2(a0.w);
            cp[3][0]=ffma2(ra,bA.x,cp[3][0]); cp[3][1]=ffma2(ra,bA.y,cp[3][1]);
            cp[3][2]=ffma2(ra,bB.x,cp[3][2]); cp[3][3]=ffma2(ra,bB.y,cp[3][3]);
            ra=rep2(a1.x);
            cp[4][0]=ffma2(ra,bA.x,cp[4][0]); cp[4][1]=ffma2(ra,bA.y,cp[4][1]);
            cp[4][2]=ffma2(ra,bB.x,cp[4][2]); cp[4][3]=ffma2(ra,bB.y,cp[4][3]);
            ra=rep2(a1.y);
            cp[5][0]=ffma2(ra,bA.x,cp[5][0]); cp[5][1]=ffma2(ra,bA.y,cp[5][1]);
            cp[5][2]=ffma2(ra,bB.x,cp[5][2]); cp[5][3]=ffma2(ra,bB.y,cp[5][3]);
            ra=rep2(a1.z);
            cp[6][0]=ffma2(ra,bA.x,cp[6][0]); cp[6][1]=ffma2(ra,bA.y,cp[6][1]);
            cp[6][2]=ffma2(ra,bB.x,cp[6][2]); cp[6][3]=ffma2(ra,bB.y,cp[6][3]);
            ra=rep2(a1.w);
            cp[7][0]=ffma2(ra,bA.x,cp[7][0]); cp[7][1]=ffma2(ra,bA.y,cp[7][1]);
            cp[7][2]=ffma2(ra,bB.x,cp[7][2]); cp[7][3]=ffma2(ra,bB.y,cp[7][3]);
        }
        __syncthreads();
    }
    float* outp = &d_efp[(size_t)slice*BNN*DD];
    int cA = tx*8 + (swb>>2);
    int cB = tx*8 + 4 - (swb>>2);
    #pragma unroll
    for(int m=0;m<8;m++){
        int row = j0 + ty*8 + m;
        ulonglong2 o1; o1.x = cp[m][0]; o1.y = cp[m][1];
        ulonglong2 o2; o2.x = cp[m][2]; o2.y = cp[m][3];
        *(ulonglong2*)&outp[row*DD + cA] = o1;
        *(ulonglong2*)&outp[row*DD + cB] = o2;
    }
}

// ---------------- K9: row-normalize [gcn; ef] + zero CSR counters -----------
__global__ void k_gnorm(){
    int t = threadIdx.x;
    int gid = blockIdx.x*256 + t;
    if(gid < BNN){ d_cnt[gid] = 0; d_cur[gid] = 0; }
    int g = t>>6, d = t&63;
    int r = blockIdx.x*4 + g;
    __shared__ float sb[8];
    float v;
    if(r < BNN) v = d_g[r*DD + d];
    else {
        int rr = r - BNN;
        v = 0.f;
        #pragma unroll
        for(int s=0; s<NSLICE; s++) v += d_efp[(size_t)s*BNN*DD + rr*DD + d];
    }
    float ss = v*v;
    #pragma unroll
    for(int o=16;o>0;o>>=1) ss += __shfl_down_sync(0xffffffffu, ss, o);
    if((t&31)==0) sb[t>>5] = ss;
    __syncthreads();
    float inv = 1.f/fmaxf(sqrtf(sb[2*g]+sb[2*g+1]), 1e-12f);
    d_gn[r*DD + d] = v*inv;
}

// ---------------- K10: S = Gn[:BN] @ Gn^T (128x128 tiles, broadcast map) ----
#define SG_SMEM (2*64*132*4)   // 67.6 KB
__global__ void __launch_bounds__(128) k_sgemm(){
    extern __shared__ float smp[];
    float* As = smp;             // [64][132] transposed: [k][m]
    float* Bs = smp + 64*132;    // [64][132] transposed: [k][n]
    int t = threadIdx.x;
    int j0 = blockIdx.x*128, i0 = blockIdx.y*128;
    #pragma unroll
    for(int u=0; u<16; u++){
        float4 va = *(const float4*)&d_gn[(i0+t)*DD + u*4];
        As[(u*4+0)*132+t]=va.x; As[(u*4+1)*132+t]=va.y;
        As[(u*4+2)*132+t]=va.z; As[(u*4+3)*132+t]=va.w;
        float4 vb = *(const float4*)&d_gn[(j0+t)*DD + u*4];
        Bs[(u*4+0)*132+t]=vb.x; Bs[(u*4+1)*132+t]=vb.y;
        Bs[(u*4+2)*132+t]=vb.z; Bs[(u*4+3)*132+t]=vb.w;
    }
    __syncthreads();
    int tx = t & 7, ty = t >> 3;   // tx: 4-col group base (x4 strided), ty: m octet
    ull acc[8][8] = {};
    #pragma unroll
    for(int k=0; k<64; k++){
        float4 a0 = *(float4*)&As[k*132 + ty*8];
        float4 a1 = *(float4*)&As[k*132 + ty*8 + 4];
        ulonglong2 b0 = *(ulonglong2*)&Bs[k*132 + tx*4];
        ulonglong2 b1 = *(ulonglong2*)&Bs[k*132 + tx*4 + 32];
        ulonglong2 b2 = *(ulonglong2*)&Bs[k*132 + tx*4 + 64];
        ulonglong2 b3 = *(ulonglong2*)&Bs[k*132 + tx*4 + 96];
        float ar[8] = {a0.x,a0.y,a0.z,a0.w,a1.x,a1.y,a1.z,a1.w};
        #pragma unroll
        for(int m=0;m<8;m++){
            ull ra = rep2(ar[m]);
            acc[m][0]=ffma2(ra,b0.x,acc[m][0]); acc[m][1]=ffma2(ra,b0.y,acc[m][1]);
            acc[m][2]=ffma2(ra,b1.x,acc[m][2]); acc[m][3]=ffma2(ra,b1.y,acc[m][3]);
            acc[m][4]=ffma2(ra,b2.x,acc[m][4]); acc[m][5]=ffma2(ra,b2.y,acc[m][5]);
            acc[m][6]=ffma2(ra,b3.x,acc[m][6]); acc[m][7]=ffma2(ra,b3.y,acc[m][7]);
        }
    }
    #pragma unroll
    for(int m=0;m<8;m++){
        int row = i0 + ty*8 + m;
        size_t base = (size_t)row*G2 + j0 + tx*4;
        #pragma unroll
        for(int q=0; q<4; q++){
            ulonglong2 o; o.x = acc[m][q*2]; o.y = acc[m][q*2+1];
            *(ulonglong2*)&d_S[base + q*32] = o;
        }
    }
}

// ---------------- K11: top-25 per row via exact 4-round radix select --------
__global__ void k_top25(){
    int r = blockIdx.x, t = threadIdx.x;     // 256 threads
    unsigned e[32];
    #pragma unroll
    for(int u=0; u<8; u++){
        float4 f = *(const float4*)&d_S[(size_t)r*G2 + (t + u*256)*4];
        e[u*4+0] = fenc(f.x); e[u*4+1] = fenc(f.y);
        e[u*4+2] = fenc(f.z); e[u*4+3] = fenc(f.w);
    }
    __shared__ unsigned hist[256];
    __shared__ unsigned spref;
    __shared__ int sneed, epos, eqn;
    __shared__ int eqlist[64];
    if(t==0){ spref=0u; sneed=EX; epos=0; eqn=0; }
    for(int round=0; round<4; round++){
        hist[t] = 0;
        __syncthreads();
        unsigned pref = spref;
        int shift = 24 - 8*round;
        if(round==0){
            #pragma unroll
            for(int u=0;u<32;u++) atomicAdd(&hist[e[u]>>24], 1u);
        } else {
            int hshift = shift + 8;
            #pragma unroll
            for(int u=0;u<32;u++)
                if((e[u]>>hshift) == pref) atomicAdd(&hist[(e[u]>>shift)&255u], 1u);
        }
        __syncthreads();
        if(t < 32){
            int need = sneed;
            unsigned hv[8]; unsigned p0 = 0;
            #pragma unroll
            for(int q=0;q<8;q++){ hv[q]=hist[t*8+q]; p0+=hv[q]; }
            unsigned s = p0;
            #pragma unroll
            for(int o=1;o<32;o<<=1){
                unsigned vv = __shfl_down_sync(0xffffffffu, s, o);
                if(t+o < 32) s += vv;
            }
            unsigned cum = s - p0;              // count of values in higher lanes
            #pragma unroll
            for(int q=7;q>=0;q--){
                unsigned nc = cum + hv[q];
                if(cum < (unsigned)need && nc >= (unsigned)need){
                    spref = (pref<<8) | (unsigned)(t*8+q);
                    sneed = need - (int)cum;
                }
                cum = nc;
            }
        }
        __syncthreads();
    }
    unsigned T = spref; int needEq = sneed;
    #pragma unroll
    for(int u=0; u<8; u++){
        #pragma unroll
        for(int j=0; j<4; j++){
            unsigned ev = e[u*4+j];
            if(ev >= T){
                int idx = (t + u*256)*4 + j;
                if(ev > T){
                    int p = atomicAdd(&epos, 1);
                    d_topv2[r*EX+p] = fdec(ev);
                    d_topi2[r*EX+p] = idx;
                    if(idx < BNN) atomicAdd(&d_cnt[idx], 1);
                } else {
                    int q = atomicAdd(&eqn, 1);
                    if(q < 64) eqlist[q] = idx;
                }
            }
        }
    }
    __syncthreads();
    if(t==0){
        int base = epos;                 // == EX - needEq
        int n = eqn < 64 ? eqn : 64;
        for(int s2=0; s2<needEq; s2++){
            int bi = 0x7fffffff, bq = 0;
            for(int q=0; q<n; q++) if(eqlist[q] < bi){ bi = eqlist[q]; bq = q; }
            eqlist[bq] = 0x7fffffff;
            d_topv2[r*EX+base+s2] = fdec(T);
            d_topi2[r*EX+base+s2] = bi;
            if(bi < BNN) atomicAdd(&d_cnt[bi], 1);
        }
    }
}

// ---------------- K12: h2 = g[:BN] @ W2 + attention scalars (4 rows/blk) ----
__global__ void k_h2(const float* __restrict__ W2,
                     const float* __restrict__ ai2, const float* __restrict__ aj2){
    int t = threadIdx.x;
    int g = t>>6, d = t&63;
    int r = blockIdx.x*4 + g;
    __shared__ float sg[4][DD];
    __shared__ float svi[8], svj[8];
    sg[g][d] = d_g[r*DD + d];
    __syncthreads();
    float h = 0.f;
    #pragma unroll
    for(int k=0;k<DD;k++) h += sg[g][k]*W2[k*DD + d];
    d_h2[r*DD + d] = h;
    float vi = h*ai2[d], vj = h*aj2[d];
    #pragma unroll
    for(int o=16;o>0;o>>=1){
        vi += __shfl_down_sync(0xffffffffu, vi, o);
        vj += __shfl_down_sync(0xffffffffu, vj, o);
    }
    if((t&31)==0){ svi[t>>5]=vi; svj[t>>5]=vj; }
    __syncthreads();
    if(d==0){ d_hi2[r] = svi[2*g]+svi[2*g+1]; d_hj2[r] = svj[2*g]+svj[2*g+1]; }
}

// ---------------- K13/K14: CSR build (scan + scatter) -----------------------
__global__ void k_scan(){       // single block, 256 threads
    __shared__ int ss[256];
    int t = threadIdx.x;
    if(t < DD){ d_sum2[t] = 0.f; d_ssq2[t] = 0.f; }
    int c[16]; int s = 0;
    #pragma unroll
    for(int i=0;i<16;i++){ int x = d_cnt[t*16+i]; c[i] = s; s += x; }
    ss[t] = s;
    __syncthreads();
    for(int off=1; off<256; off<<=1){
        int v = (t>=off) ? ss[t-off] : 0;
        __syncthreads();
        ss[t] += v;
        __syncthreads();
    }
    int base = (t==0) ? 0 : ss[t-1];
    #pragma unroll
    for(int i=0;i<16;i++) d_off[t*16+i] = base + c[i];
    if(t==255) d_off[BNN] = ss[255];
}
__global__ void k_scatter(){
    int e = blockIdx.x*256 + threadIdx.x;
    int dst = d_topi2[e];
    if(dst < BNN){
        int p = atomicAdd(&d_cur[dst], 1);
        d_eid[d_off[dst] + p] = e;
    }
}

// ---------------- K15: segment softmax + gather + x3 + BN stats accum -------
__global__ void k_seg(const float* __restrict__ bias2, const float* __restrict__ emb){
    int r = blockIdx.x, t = threadIdx.x;    // 64 threads
    int start = d_off[r], end = d_off[r+1];
    __shared__ float sred[2];
    __shared__ float sal[64];
    __shared__ int   ssrc[64];
    float hi = d_hi2[r];
    float m = -INFINITY;
    for(int e=start+t; e<end; e+=64){
        int eid = d_eid[e]; int src = eid/EX;
        float sc = lrelu(hi + d_hj2[src]) * d_topv2[eid];
        d_sc2[e] = sc;
        m = fmaxf(m, sc);
    }
    #pragma unroll
    for(int o=16;o>0;o>>=1) m = fmaxf(m, __shfl_down_sync(0xffffffffu, m, o));
    if((t&31)==0) sred[t>>5] = m;
    __syncthreads();
    m = fmaxf(sred[0], sred[1]);
    __syncthreads();
    float s = 0.f;
    for(int e=start+t; e<end; e+=64) s += expf(d_sc2[e]-m);
    #pragma unroll
    for(int o=16;o>0;o>>=1) s += __shfl_down_sync(0xffffffffu, s, o);
    if((t&31)==0) sred[t>>5] = s;
    __syncthreads();
    float inv = 1.f/fmaxf(sred[0]+sred[1], 1e-12f);
    float acc = 0.f;
    for(int c0=start; c0<end; c0+=64){
        __syncthreads();
        int e = c0 + t;
        if(e < end){
            int eid = d_eid[e];
            ssrc[t] = eid/EX;
            sal[t]  = expf(d_sc2[e]-m)*inv;
        }
        __syncthreads();
        int cnt = min(64, end - c0);
        for(int k=0;k<cnt;k++) acc += sal[k]*d_h2[ssrc[k]*DD + t];
    }
    float x = fmaxf(acc + bias2[t], 0.f);
    float x3v = x * emb[(r & (NN-1))*DD + t];
    d_x3[r*DD + t] = x3v;
    atomicAdd(&d_sum2[t], x3v);
    atomicAdd(&d_ssq2[t], x3v*x3v);
}

// ---------------- K17: output head (4 rows/block, inline BN) ----------------
__global__ void k_out(const float* __restrict__ gamma, const float* __restrict__ beta,
                      const float* __restrict__ Wout, const float* __restrict__ bout,
                      float* __restrict__ out){
    int t = threadIdx.x;
    int g = t>>6, d = t&63;
    int r = blockIdx.x*4 + g;
    __shared__ float sb[8];
    float mu  = d_sum2[d]*(1.f/BNN);
    float var = d_ssq2[d]*(1.f/BNN) - mu*mu;
    float sc  = gamma[d]/sqrtf(var + 1e-5f);
    float sh  = beta[d] - mu*sc;
    float x = fmaxf(sc*d_x3[r*DD + d] + sh, 0.f);
    float v = x * Wout[d];
    #pragma unroll
    for(int o=16;o>0;o>>=1) v += __shfl_down_sync(0xffffffffu, v, o);
    if((t&31)==0) sb[t>>5] = v;
    __syncthreads();
    if(d==0) out[r] = sb[2*g]+sb[2*g+1] + bout[0];
}

// ---------------- launch ----------------
extern "C" void kernel_launch(void* const* d_in, const int* in_sizes, int n_in,
                              void* d_out, int out_size){
    (void)in_sizes; (void)n_in; (void)out_size;
    const float* data  = (const float*)d_in[0];
    const float* emb   = (const float*)d_in[1];
    const float* W1    = (const float*)d_in[2];
    const float* ai1   = (const float*)d_in[3];
    const float* aj1   = (const float*)d_in[4];
    const float* bias1 = (const float*)d_in[5];
    const float* bn1g  = (const float*)d_in[6];
    const float* bn1b  = (const float*)d_in[7];
    const float* P     = (const float*)d_in[8];
    const float* W2    = (const float*)d_in[9];
    const float* ai2   = (const float*)d_in[10];
    const float* aj2   = (const float*)d_in[11];
    const float* bias2 = (const float*)d_in[12];
    const float* bnOg  = (const float*)d_in[13];
    const float* bnOb  = (const float*)d_in[14];
    const float* Wout  = (const float*)d_in[15];
    const float* bout  = (const float*)d_in[16];
    float* out = (float*)d_out;

    static int smem_set = 0;
    if(!smem_set){
        cudaFuncSetAttribute(k_ef, cudaFuncAttributeMaxDynamicSharedMemorySize, EF_SMEM);
        cudaFuncSetAttribute(k_sgemm, cudaFuncAttributeMaxDynamicSharedMemorySize, SG_SMEM);
        smem_set = 1;
    }

    k_embprep <<<NN, DD>>>(emb, ai1, aj1);
    k_cos1    <<<NN, NN>>>(emb);
    k_h       <<<BNN/4, 256>>>(data, W1, ai1, aj1);
    k_attn1   <<<BNN/4, 256>>>(bias1);
    k_bnrelu  <<<BNN*DD/256, 256>>>(bn1g, bn1b);
    k_ef      <<<dim3(32, NSLICE), 128, EF_SMEM>>>(P);
    k_gnorm   <<<G2/4, 256>>>();
    k_sgemm   <<<dim3(64, 32), 128, SG_SMEM>>>();
    k_top25   <<<BNN, 256>>>();
    k_h2      <<<BNN/4, 256>>>(W2, ai2, aj2);
    k_scan    <<<1, 256>>>();
    k_scatter <<<NE/256, 256>>>();
    k_seg     <<<BNN, 64>>>(bias2, emb);
    k_out     <<<BNN/4, 256>>>(bnOg, bnOb, Wout, bout, out);
}